// round 10
// baseline (speedup 1.0000x reference)
#include <cuda_runtime.h>
#include <cuda_fp16.h>
#include <math.h>
#include <stdint.h>

// Problem constants
#define BB   1024
#define DM   512
#define NH   8
#define HD   64
#define NN   81
#define OC   1536

// Fused tiling: CTA = (b, h); A rows = 64 Q + 64 K + 64 V for head h
#define MT     192
#define NT     96            // padded n (81 -> 96)
#define KT     32            // k per pipeline stage (64B rows)
#define NTILES (DM / KT)     // 16
#define NSTG   2

#define RSTRIDE 80           // 64B data + 16B pad (ldmatrix conflict-free)
#define APL  (MT * RSTRIDE)             // 15360
#define BPL  (NT * RSTRIDE)             // 7680
#define STG_BYTES (APL + BPL)           // 23040
#define STAGES_BYTES (NSTG * STG_BYTES) // 46080

// attention smem planes
#define QP    68             // floats per Q/K/V row (17 float4)
#define SP    84             // floats per S row
#define NROWS 82
#define PLANE (NROWS * QP)
#define QKV_OFF STAGES_BYTES
#define SMEM_FUSED (QKV_OFF + 3 * PLANE * 4)   // 112992 B -> 2 CTAs/SM

// Scratch (fp16 inputs only)
__device__ __half g_wh[(size_t)OC * DM];
__device__ __half g_xh[(size_t)BB * NT * DM];

typedef unsigned long long ull;

__device__ __forceinline__ uint32_t smem_u32(const void* p) {
    uint32_t a;
    asm("{ .reg .u64 t; cvta.to.shared.u64 t, %1; cvt.u32.u64 %0, t; }" : "=r"(a) : "l"(p));
    return a;
}

__device__ __forceinline__ void fma2(ull& c, ull a, ull b) {
    asm("fma.rn.f32x2 %0, %1, %2, %0;" : "+l"(c) : "l"(a), "l"(b));
}
__device__ __forceinline__ float hsum2(ull v) {
    float lo, hi;
    asm("mov.b64 {%0, %1}, %2;" : "=f"(lo), "=f"(hi) : "l"(v));
    return lo + hi;
}
__device__ __forceinline__ ull bcast2(float x) {
    ull r;
    asm("mov.b64 %0, {%1, %1};" : "=l"(r) : "f"(x));
    return r;
}
__device__ __forceinline__ void unpack2(ull v, float& lo, float& hi) {
    asm("mov.b64 {%0, %1}, %2;" : "=f"(lo), "=f"(hi) : "l"(v));
}

#define CP16(dst, src) \
    asm volatile("cp.async.cg.shared.global [%0], [%1], 16;" :: "r"(dst), "l"(src))
#define CP_COMMIT() asm volatile("cp.async.commit_group;" ::: "memory")
#define CP_WAIT(n)  asm volatile("cp.async.wait_group %0;" :: "n"(n) : "memory")

#define LDSM4(r0, r1, r2, r3, addr)                                           \
    asm volatile("ldmatrix.sync.aligned.m8n8.x4.shared.b16 {%0,%1,%2,%3}, [%4];" \
        : "=r"(r0), "=r"(r1), "=r"(r2), "=r"(r3) : "r"(addr))

#define MMA_F16(C, A, B)                                                      \
    asm volatile(                                                             \
        "mma.sync.aligned.m16n8k16.row.col.f32.f16.f16.f32 "                  \
        "{%0,%1,%2,%3}, {%4,%5,%6,%7}, {%8,%9}, {%0,%1,%2,%3};\n"             \
        : "+f"((C)[0]), "+f"((C)[1]), "+f"((C)[2]), "+f"((C)[3])              \
        : "r"((A)[0]), "r"((A)[1]), "r"((A)[2]), "r"((A)[3]),                 \
          "r"((B)[0]), "r"((B)[1]))

// ---------------------------------------------------------------------------
__global__ void prep_w(const float* __restrict__ w) {
    int i = blockIdx.x * 256 + threadIdx.x;
    g_wh[i] = __float2half_rn(w[i]);
}

__global__ __launch_bounds__(256) void prep_x(const float* __restrict__ x) {
    __shared__ float ts[64][83];
    const int b  = blockIdx.x;
    const int c0 = blockIdx.y * 64;
    const int tid = threadIdx.x;

    const float* xb = x + ((size_t)b * DM + c0) * NN;
    for (int idx = tid; idx < 64 * NN; idx += 256) {
        int c = idx / NN;
        int n = idx - c * NN;
        ts[c][n] = xb[(size_t)c * NN + n];
    }
    __syncthreads();

    for (int idx = tid; idx < NT * 64; idx += 256) {
        int n = idx >> 6;
        int c = idx & 63;
        float v = (n < NN) ? ts[c][n] : 0.0f;
        g_xh[((size_t)b * NT + n) * DM + c0 + c] = __float2half_rn(v);
    }
}

// ---------------------------------------------------------------------------
__device__ __forceinline__ void load_stage(uint32_t sb, int stage,
                                           int k0, int h64, int b, int tid) {
    const uint32_t base = sb + stage * STG_BYTES;
#pragma unroll
    for (int i = 0; i < 3; i++) {                // A: 768 chunks
        int idx = tid + i * 256;
        int row = idx >> 2;
        int chv = idx & 3;
        int o   = (row >> 6) * DM + h64 + (row & 63);
        const __half* src = g_wh + (size_t)o * DM + k0 + chv * 8;
        CP16(base + row * RSTRIDE + chv * 16, src);
    }
#pragma unroll
    for (int i = 0; i < 2; i++) {                // B: 384 chunks
        int idx = tid + i * 256;
        if (idx < 384) {
            int row = idx >> 2;
            int chv = idx & 3;
            const __half* src = g_xh + ((size_t)b * NT + row) * DM + k0 + chv * 8;
            CP16(base + APL + row * RSTRIDE + chv * 16, src);
        }
    }
    CP_COMMIT();
}

// ---------------------------------------------------------------------------
// Fused kernel: per (b,h) QKV projection (fp16 HMMA) + attention (fp32/FFMA2)
// ---------------------------------------------------------------------------
__global__ __launch_bounds__(256, 2) void fused_mhsa(const float* __restrict__ bias,
                                                     const float* __restrict__ rel_h,
                                                     const float* __restrict__ rel_w,
                                                     float* __restrict__ out) {
    extern __shared__ char smem[];
    const uint32_t sb = smem_u32(smem);
    float* Qs = (float*)(smem + QKV_OFF);     // [82][68]
    float* Ks = Qs + PLANE;
    float* Vs = Ks + PLANE;
    float* S  = (float*)smem;                 // aliases GEMM stages, [82][84]

    const int tid  = threadIdx.x;
    const int bh   = blockIdx.x;
    const int b    = bh >> 3;
    const int h    = bh & 7;
    const int h64  = h * HD;
    const int warp = tid >> 5;
    const int lane = tid & 31;
    const int wm   = warp & 3;
    const int wn   = warp >> 2;
    const int g    = lane >> 2;
    const int l4   = lane & 3;

    const uint32_t aoff = ((lane & 7) + ((lane >> 3) & 1) * 8) * RSTRIDE + (lane >> 4) * 16;
    const uint32_t boff = ((lane & 7) + ((lane >> 4) & 1) * 8) * RSTRIDE + ((lane >> 3) & 1) * 16;

    float acc[3][6][4];
#pragma unroll
    for (int i = 0; i < 3; i++)
#pragma unroll
        for (int j = 0; j < 6; j++)
#pragma unroll
            for (int r = 0; r < 4; r++) acc[i][j][r] = 0.0f;

    // ------------------- GEMM phase -------------------
    load_stage(sb, 0, 0, h64, b, tid);
    load_stage(sb, 1, KT, h64, b, tid);

    for (int ch = 0; ch < NTILES; ch++) {
        if (ch + 1 < NTILES) { CP_WAIT(1); } else { CP_WAIT(0); }
        __syncthreads();

        const uint32_t st = sb + (ch & 1) * STG_BYTES;
        const uint32_t sA = st;
        const uint32_t sB = st + APL;

#pragma unroll
        for (int ks = 0; ks < 2; ks++) {
            uint32_t a[3][4];
#pragma unroll
            for (int mi = 0; mi < 3; mi++) {
                uint32_t ra = (uint32_t)((wm * 48 + mi * 16) * RSTRIDE + ks * 32) + aoff;
                LDSM4(a[mi][0], a[mi][1], a[mi][2], a[mi][3], sA + ra);
            }
            uint32_t bf[3][4];
#pragma unroll
            for (int pr = 0; pr < 3; pr++) {
                uint32_t rb = (uint32_t)((wn * 48 + pr * 16) * RSTRIDE + ks * 32) + boff;
                LDSM4(bf[pr][0], bf[pr][1], bf[pr][2], bf[pr][3], sB + rb);
            }
#pragma unroll
            for (int pr = 0; pr < 3; pr++)
#pragma unroll
                for (int sub = 0; sub < 2; sub++)
#pragma unroll
                    for (int mi = 0; mi < 3; mi++)
                        MMA_F16(acc[mi][pr * 2 + sub], a[mi], bf[pr] + sub * 2);
        }

        if (ch + 2 < NTILES) {
            __syncthreads();
            load_stage(sb, ch & 1, (ch + 2) * KT, h64, b, tid);
        }
    }

    // ---- Epilogue: accs -> smem planes [n][d] (V as-is); bias + rel fold ----
#pragma unroll
    for (int mi = 0; mi < 3; mi++) {
#pragma unroll
        for (int rr = 0; rr < 2; rr++) {
            const int row = wm * 48 + mi * 16 + g + rr * 8;
            const int grp = row >> 6;
            const int d   = row & 63;
            const float bv = bias[grp * DM + h64 + d];
            float* plane = (grp == 0) ? Qs : (grp == 1) ? Ks : Vs;
#pragma unroll
            for (int f = 0; f < 6; f++) {
                const int n0 = wn * 48 + f * 8 + 2 * l4;
#pragma unroll
                for (int cc = 0; cc < 2; cc++) {
                    const int col = n0 + cc;
                    if (col < NN) {
                        float v = acc[mi][f][rr * 2 + cc] + bv;
                        if (grp == 1)
                            v += rel_h[(h64 + d) * 9 + col % 9]
                               + rel_w[(h64 + d) * 9 + col / 9];
                        plane[col * QP + d] = v;
                    }
                }
            }
        }
    }
    __syncthreads();

    // ------------------- Attention phase -------------------
    // Scores: 2x2 tiles, packed f32x2 dot over 64
    for (int t = tid; t < 41 * 41; t += 256) {
        int ti = t / 41;
        int tj = t - ti * 41;
        int n0 = 2 * ti;
        int m0 = 2 * tj;
        const ulonglong2* q0 = (const ulonglong2*)(Qs + n0 * QP);
        const ulonglong2* q1 = (const ulonglong2*)(Qs + (n0 + 1) * QP);
        const ulonglong2* k0 = (const ulonglong2*)(Ks + m0 * QP);
        const ulonglong2* k1 = (const ulonglong2*)(Ks + (m0 + 1) * QP);
        ull s00 = 0ull, s01 = 0ull, s10 = 0ull, s11 = 0ull;
#pragma unroll
        for (int dv = 0; dv < 16; dv++) {
            ulonglong2 a0 = q0[dv], a1 = q1[dv], c0 = k0[dv], c1 = k1[dv];
            fma2(s00, a0.x, c0.x); fma2(s00, a0.y, c0.y);
            fma2(s01, a0.x, c1.x); fma2(s01, a0.y, c1.y);
            fma2(s10, a1.x, c0.x); fma2(s10, a1.y, c0.y);
            fma2(s11, a1.x, c1.x); fma2(s11, a1.y, c1.y);
        }
        S[n0 * SP + m0]           = hsum2(s00);
        S[n0 * SP + m0 + 1]       = hsum2(s01);
        S[(n0 + 1) * SP + m0]     = hsum2(s10);
        S[(n0 + 1) * SP + m0 + 1] = hsum2(s11);
    }
    __syncthreads();

    // softmax: warp per row, lanes over m
    for (int r = warp; r < NN; r += 8) {
        float* row = S + r * SP;
        float mx = -1e30f;
        for (int m = lane; m < NN; m += 32) mx = fmaxf(mx, row[m]);
#pragma unroll
        for (int s = 16; s > 0; s >>= 1)
            mx = fmaxf(mx, __shfl_xor_sync(0xFFFFFFFF, mx, s));
        float sum = 0.0f;
        for (int m = lane; m < NN; m += 32) {
            float e = __expf(row[m] - mx);
            row[m] = e;
            sum += e;
        }
#pragma unroll
        for (int s = 16; s > 0; s >>= 1)
            sum += __shfl_xor_sync(0xFFFFFFFF, sum, s);
        float inv = 1.0f / sum;
        for (int m = lane; m < NN; m += 32) row[m] *= inv;
    }
    __syncthreads();

    // PV: (2 n-rows) x (4 d-cols) tiles; packed f32x2
    for (int t = tid; t < 41 * 16; t += 256) {
        int ti = t >> 4;
        int d4 = t & 15;
        int n0 = 2 * ti;
        const float* p0 = S + n0 * SP;
        const float* p1 = S + (n0 + 1) * SP;
        ull a0a = 0ull, a0b = 0ull, a1a = 0ull, a1b = 0ull;
        for (int m = 0; m < NN; m++) {
            ulonglong2 v = *(const ulonglong2*)(Vs + m * QP + 4 * d4);
            ull w0 = bcast2(p0[m]);
            ull w1 = bcast2(p1[m]);
            fma2(a0a, w0, v.x); fma2(a0b, w0, v.y);
            fma2(a1a, w1, v.x); fma2(a1b, w1, v.y);
        }
        float o00, o01, o02, o03, o10, o11, o12, o13;
        unpack2(a0a, o00, o01); unpack2(a0b, o02, o03);
        unpack2(a1a, o10, o11); unpack2(a1b, o12, o13);
        const int d = 4 * d4;
        float* o0 = out + ((size_t)b * DM + h64 + d) * NN + n0;
        o0[0]      = o00;
        o0[NN]     = o01;
        o0[2 * NN] = o02;
        o0[3 * NN] = o03;
        if (n0 + 1 < NN) {
            o0[1]          = o10;
            o0[NN + 1]     = o11;
            o0[2 * NN + 1] = o12;
            o0[3 * NN + 1] = o13;
        }
    }
}

// ---------------------------------------------------------------------------
extern "C" void kernel_launch(void* const* d_in, const int* in_sizes, int n_in,
                              void* d_out, int out_size) {
    const float* x     = (const float*)d_in[0];
    const float* qkv_w = (const float*)d_in[1];
    const float* qkv_b = (const float*)d_in[2];
    const float* rel_h = (const float*)d_in[3];
    const float* rel_w = (const float*)d_in[4];
    float* out = (float*)d_out;

    cudaFuncSetAttribute(fused_mhsa, cudaFuncAttributeMaxDynamicSharedMemorySize, SMEM_FUSED);

    prep_w<<<OC * DM / 256, 256>>>(qkv_w);
    prep_x<<<dim3(BB, DM / 64), 256>>>(x);
    fused_mhsa<<<BB * NH, 256, SMEM_FUSED>>>(qkv_b, rel_h, rel_w, out);
}

// round 11
// speedup vs baseline: 1.5949x; 1.5949x over previous
#include <cuda_runtime.h>
#include <cuda_fp16.h>
#include <math.h>
#include <stdint.h>

// Problem constants
#define BB   1024
#define DM   512
#define NH   8
#define HD   64
#define NN   81
#define OC   1536

// Phase-1 GEMM staging
#define KT     32
#define NTILES (DM / KT)     // 16
#define RSTRIDE 80           // 64B data + 16B pad
#define WROWS  192
#define XROWS  96
#define WTILE  (WROWS * RSTRIDE)        // 15360
#define XTILE  (XROWS * RSTRIDE)        // 7680
#define STG_BYTES (WTILE + XTILE)       // 23040
#define STAGES    (2 * STG_BYTES)       // 46080

// fp16 hi/lo planes
#define QKSTRIDE 144         // Q/K: 96 rows x (128B data + 16 pad)
#define VSTRIDE  208         // V: 64 rows, P: 96 rows x (192B data + 16 pad)
#define QKPLANE  (96 * QKSTRIDE)        // 13824
#define VPLANE   (64 * VSTRIDE)         // 13312
#define PPLANE   (96 * VSTRIDE)         // 19968

#define SP       84          // S row stride (floats)
#define OSTRIDE  68          // O-combine row stride (floats)

// smem map
#define R0_VH   0
#define R0_VL   VPLANE
#define R0_S    (2 * VPLANE)                 // 26624 (stages dead by then)
#define R0_O    R0_S
#define R0_SIZE (R0_S + 82 * SP * 4)         // 54176
#define OFF_QH  (R0_SIZE)
#define OFF_QL  (R0_SIZE + QKPLANE)
#define OFF_KH  (R0_SIZE + 2 * QKPLANE)
#define OFF_KL  (R0_SIZE + 3 * QKPLANE)
#define OFF_PH  (R0_SIZE)                    // P overlays Q/K after scores
#define OFF_PL  (R0_SIZE + PPLANE)
#define SMEM_FUSED (R0_SIZE + 4 * QKPLANE)   // 109472 -> 2 CTAs/SM

// Scratch (fp16 inputs only)
__device__ __half g_wh[(size_t)OC * DM];
__device__ __half g_xh[(size_t)BB * 96 * DM];

__device__ __forceinline__ uint32_t smem_u32(const void* p) {
    uint32_t a;
    asm("{ .reg .u64 t; cvta.to.shared.u64 t, %1; cvt.u32.u64 %0, t; }" : "=r"(a) : "l"(p));
    return a;
}

#define CP16(dst, src) \
    asm volatile("cp.async.cg.shared.global [%0], [%1], 16;" :: "r"(dst), "l"(src))
#define CP_COMMIT() asm volatile("cp.async.commit_group;" ::: "memory")
#define CP_WAIT(n)  asm volatile("cp.async.wait_group %0;" :: "n"(n) : "memory")

#define LDSM4(r0, r1, r2, r3, addr)                                           \
    asm volatile("ldmatrix.sync.aligned.m8n8.x4.shared.b16 {%0,%1,%2,%3}, [%4];" \
        : "=r"(r0), "=r"(r1), "=r"(r2), "=r"(r3) : "r"(addr))

#define LDSM2(r0, r1, addr)                                                   \
    asm volatile("ldmatrix.sync.aligned.m8n8.x2.shared.b16 {%0,%1}, [%2];"    \
        : "=r"(r0), "=r"(r1) : "r"(addr))

#define MMA_F16(C, A, B)                                                      \
    asm volatile(                                                             \
        "mma.sync.aligned.m16n8k16.row.col.f32.f16.f16.f32 "                  \
        "{%0,%1,%2,%3}, {%4,%5,%6,%7}, {%8,%9}, {%0,%1,%2,%3};\n"             \
        : "+f"((C)[0]), "+f"((C)[1]), "+f"((C)[2]), "+f"((C)[3])              \
        : "r"((A)[0]), "r"((A)[1]), "r"((A)[2]), "r"((A)[3]),                 \
          "r"((B)[0]), "r"((B)[1]))

// split v into fp16 hi + lo, store half2-packed pair to hi/lo planes
__device__ __forceinline__ void split_store(char* smem, int offH, int offL,
                                            int byteoff, float v0, float v1) {
    __half h0 = __float2half_rn(v0);
    __half h1 = __float2half_rn(v1);
    float  l0 = v0 - __half2float(h0);
    float  l1 = v1 - __half2float(h1);
    *(__half2*)(smem + offH + byteoff) = __halves2half2(h0, h1);
    *(__half2*)(smem + offL + byteoff) =
        __halves2half2(__float2half_rn(l0), __float2half_rn(l1));
}

// ---------------------------------------------------------------------------
__global__ void prep_w(const float* __restrict__ w) {
    int i = blockIdx.x * 256 + threadIdx.x;
    g_wh[i] = __float2half_rn(w[i]);
}

__global__ __launch_bounds__(256) void prep_x(const float* __restrict__ x) {
    __shared__ float ts[64][83];
    const int b  = blockIdx.x;
    const int c0 = blockIdx.y * 64;
    const int tid = threadIdx.x;

    const float* xb = x + ((size_t)b * DM + c0) * NN;
    for (int idx = tid; idx < 64 * NN; idx += 256) {
        int c = idx / NN;
        int n = idx - c * NN;
        ts[c][n] = xb[(size_t)c * NN + n];
    }
    __syncthreads();

    for (int idx = tid; idx < 96 * 64; idx += 256) {
        int n = idx >> 6;
        int c = idx & 63;
        float v = (n < NN) ? ts[c][n] : 0.0f;
        g_xh[((size_t)b * 96 + n) * DM + c0 + c] = __float2half_rn(v);
    }
}

// ---------------------------------------------------------------------------
// Stage loader: W rows (Q|K|V for head h) + X rows for batch b
// ---------------------------------------------------------------------------
__device__ __forceinline__ void load_stage(uint32_t sb, int stage,
                                           int k0, int h64, int b, int tid) {
    const uint32_t base = sb + stage * STG_BYTES;
#pragma unroll
    for (int i = 0; i < 3; i++) {                // W: 768 chunks
        int idx = tid + i * 256;
        int row = idx >> 2;
        int chv = idx & 3;
        int o   = (row >> 6) * DM + h64 + (row & 63);
        const __half* src = g_wh + (size_t)o * DM + k0 + chv * 8;
        CP16(base + row * RSTRIDE + chv * 16, src);
    }
#pragma unroll
    for (int i = 0; i < 2; i++) {                // X: 384 chunks
        int idx = tid + i * 256;
        if (idx < 384) {
            int row = idx >> 2;
            int chv = idx & 3;
            const __half* src = g_xh + ((size_t)b * 96 + row) * DM + k0 + chv * 8;
            CP16(base + WTILE + row * RSTRIDE + chv * 16, src);
        }
    }
    CP_COMMIT();
}

// ---------------------------------------------------------------------------
// Fused kernel: QKV GEMM + scores + softmax + PV, all matmuls on fp16 HMMA.
// ---------------------------------------------------------------------------
__global__ __launch_bounds__(256, 2) void fused_mhsa(const float* __restrict__ bias,
                                                     const float* __restrict__ rel_h,
                                                     const float* __restrict__ rel_w,
                                                     float* __restrict__ out) {
    extern __shared__ char smem[];
    const uint32_t sb = smem_u32(smem);
    float* Sf = (float*)(smem + R0_S);
    float* Of = (float*)(smem + R0_O);

    const int tid  = threadIdx.x;
    const int bh   = blockIdx.x;
    const int b    = bh >> 3;
    const int h64  = (bh & 7) * HD;
    const int warp = tid >> 5;
    const int lane = tid & 31;
    const int g    = lane >> 2;
    const int l4   = lane & 3;

    const uint32_t arow = (lane & 7) + ((lane >> 3) & 1) * 8;
    const uint32_t acol = (lane >> 4) * 16;
    const uint32_t brow = (lane & 7) + ((lane >> 4) & 1) * 8;
    const uint32_t bcol = ((lane >> 3) & 1) * 16;
    const uint32_t aoff80  = arow * 80  + acol;
    const uint32_t boff80  = brow * 80  + bcol;
    const uint32_t aoff144 = arow * 144 + acol;
    const uint32_t boff144 = brow * 144 + bcol;
    const uint32_t aoff208 = arow * 208 + acol;
    const uint32_t boff208 = brow * 208 + bcol;

    // ================= Phase 1: QKV projection =================
    // QK: out[token][o]  (A = X, M=96 tokens; B = Wqk, N=128)
    // V : out[d][token]  (A = Wv, M=64; B = X, N=96)
    const int wA = warp & 1;    // M half
    const int wB = warp >> 1;   // N quarter (0..3)

    float qk[3][4][4];
    float vv[2][3][4];
#pragma unroll
    for (int i = 0; i < 3; i++)
#pragma unroll
        for (int j = 0; j < 4; j++)
#pragma unroll
            for (int r = 0; r < 4; r++) qk[i][j][r] = 0.0f;
#pragma unroll
    for (int i = 0; i < 2; i++)
#pragma unroll
        for (int j = 0; j < 3; j++)
#pragma unroll
            for (int r = 0; r < 4; r++) vv[i][j][r] = 0.0f;

    load_stage(sb, 0, 0, h64, b, tid);
    load_stage(sb, 1, KT, h64, b, tid);

    for (int ch = 0; ch < NTILES; ch++) {
        if (ch + 1 < NTILES) { CP_WAIT(1); } else { CP_WAIT(0); }
        __syncthreads();

        const uint32_t Wt = sb + (ch & 1) * STG_BYTES;
        const uint32_t Xt = Wt + WTILE;

#pragma unroll
        for (int ks = 0; ks < 2; ks++) {
            const uint32_t kb = ks * 32;
            // --- QK ---
            uint32_t a[3][4];
#pragma unroll
            for (int mi = 0; mi < 3; mi++)
                LDSM4(a[mi][0], a[mi][1], a[mi][2], a[mi][3],
                      Xt + (uint32_t)((wA * 48 + mi * 16) * 80) + kb + aoff80);
            uint32_t bw[2][4];
#pragma unroll
            for (int pr = 0; pr < 2; pr++)
                LDSM4(bw[pr][0], bw[pr][1], bw[pr][2], bw[pr][3],
                      Wt + (uint32_t)((wB * 32 + pr * 16) * 80) + kb + boff80);
#pragma unroll
            for (int pr = 0; pr < 2; pr++)
#pragma unroll
                for (int sub = 0; sub < 2; sub++)
#pragma unroll
                    for (int mi = 0; mi < 3; mi++)
                        MMA_F16(qk[mi][pr * 2 + sub], a[mi], bw[pr] + 2 * sub);
            // --- V ---
            uint32_t av[2][4];
#pragma unroll
            for (int mi = 0; mi < 2; mi++)
                LDSM4(av[mi][0], av[mi][1], av[mi][2], av[mi][3],
                      Wt + (uint32_t)((128 + wA * 32 + mi * 16) * 80) + kb + aoff80);
            uint32_t bx0[4], bx2[2];
            LDSM4(bx0[0], bx0[1], bx0[2], bx0[3],
                  Xt + (uint32_t)((wB * 24) * 80) + kb + boff80);
            LDSM2(bx2[0], bx2[1],
                  Xt + (uint32_t)((wB * 24 + 16 + (lane & 7)) * 80) + kb
                     + ((lane >> 3) & 1) * 16);
#pragma unroll
            for (int mi = 0; mi < 2; mi++) {
                MMA_F16(vv[mi][0], av[mi], bx0 + 0);
                MMA_F16(vv[mi][1], av[mi], bx0 + 2);
                MMA_F16(vv[mi][2], av[mi], bx2);
            }
        }

        if (ch + 2 < NTILES) {
            __syncthreads();
            load_stage(sb, ch & 1, (ch + 2) * KT, h64, b, tid);
        }
    }
    __syncthreads();   // stages dead; V epilogue reuses that space

    // ---- Epilogue 1a: Q/K accums -> fp16 hi/lo planes [token][d] ----
#pragma unroll
    for (int mi = 0; mi < 3; mi++) {
#pragma unroll
        for (int rr = 0; rr < 2; rr++) {
            const int tok = wA * 48 + mi * 16 + g + rr * 8;
            const int tc  = (tok < NN) ? tok : 80;
#pragma unroll
            for (int ni = 0; ni < 4; ni++) {
                const int o  = wB * 32 + ni * 8 + 2 * l4;
                float c0 = qk[mi][ni][rr * 2 + 0];
                float c1 = qk[mi][ni][rr * 2 + 1];
                if (wB < 2) {          // Q
                    c0 += bias[h64 + o];
                    c1 += bias[h64 + o + 1];
                    split_store(smem, OFF_QH, OFF_QL, tok * QKSTRIDE + 2 * o, c0, c1);
                } else {               // K (+rel fold)
                    const int d = o - 64;
                    c0 += bias[512 + h64 + d]
                        + rel_h[(h64 + d) * 9 + tc % 9] + rel_w[(h64 + d) * 9 + tc / 9];
                    c1 += bias[512 + h64 + d + 1]
                        + rel_h[(h64 + d + 1) * 9 + tc % 9] + rel_w[(h64 + d + 1) * 9 + tc / 9];
                    split_store(smem, OFF_KH, OFF_KL, tok * QKSTRIDE + 2 * d, c0, c1);
                }
            }
        }
    }
    // ---- Epilogue 1b: V accums -> fp16 hi/lo planes [d][token] ----
#pragma unroll
    for (int mi = 0; mi < 2; mi++) {
#pragma unroll
        for (int rr = 0; rr < 2; rr++) {
            const int d  = wA * 32 + mi * 16 + g + rr * 8;
            const float bv = bias[1024 + h64 + d];
#pragma unroll
            for (int ni = 0; ni < 3; ni++) {
                const int tok = wB * 24 + ni * 8 + 2 * l4;
                split_store(smem, R0_VH, R0_VL, d * VSTRIDE + 2 * tok,
                            vv[mi][ni][rr * 2] + bv, vv[mi][ni][rr * 2 + 1] + bv);
            }
        }
    }
    __syncthreads();

    // ================= Phase 2: scores S = Q.K^T (3-term fp16) =================
    {
        const int sn = warp & 1;          // n half (48)
        const int sm = (warp >> 1) & 1;   // m half (48)
        const int sk = warp >> 2;         // k half (d 32)
        float sc[3][6][4];
#pragma unroll
        for (int i = 0; i < 3; i++)
#pragma unroll
            for (int j = 0; j < 6; j++)
#pragma unroll
                for (int r = 0; r < 4; r++) sc[i][j][r] = 0.0f;

#pragma unroll
        for (int t = 0; t < 3; t++) {
            const uint32_t Ap = sb + ((t < 2) ? OFF_QH : OFF_QL);
            const uint32_t Bp = sb + ((t == 1) ? OFF_KL : OFF_KH);
#pragma unroll
            for (int ks = 0; ks < 2; ks++) {
                const uint32_t kb = sk * 64 + ks * 32;
                uint32_t a[3][4];
#pragma unroll
                for (int mi = 0; mi < 3; mi++)
                    LDSM4(a[mi][0], a[mi][1], a[mi][2], a[mi][3],
                          Ap + (uint32_t)((sn * 48 + mi * 16) * QKSTRIDE) + kb + aoff144);
                uint32_t bk[3][4];
#pragma unroll
                for (int pr = 0; pr < 3; pr++)
                    LDSM4(bk[pr][0], bk[pr][1], bk[pr][2], bk[pr][3],
                          Bp + (uint32_t)((sm * 48 + pr * 16) * QKSTRIDE) + kb + boff144);
#pragma unroll
                for (int pr = 0; pr < 3; pr++)
#pragma unroll
                    for (int sub = 0; sub < 2; sub++)
#pragma unroll
                        for (int mi = 0; mi < 3; mi++)
                            MMA_F16(sc[mi][pr * 2 + sub], a[mi], bk[pr] + 2 * sub);
            }
        }
        // combine k-halves into S (two passes)
        if (sk == 0) {
#pragma unroll
            for (int mi = 0; mi < 3; mi++)
#pragma unroll
                for (int nj = 0; nj < 6; nj++)
#pragma unroll
                    for (int rr = 0; rr < 2; rr++) {
                        const int n = sn * 48 + mi * 16 + g + rr * 8;
                        const int m = sm * 48 + nj * 8 + 2 * l4;
                        if (n < 82 && m < 82)
                            *(float2*)(Sf + n * SP + m) =
                                make_float2(sc[mi][nj][rr * 2], sc[mi][nj][rr * 2 + 1]);
                    }
        }
        __syncthreads();
        if (sk == 1) {
#pragma unroll
            for (int mi = 0; mi < 3; mi++)
#pragma unroll
                for (int nj = 0; nj < 6; nj++)
#pragma unroll
                    for (int rr = 0; rr < 2; rr++) {
                        const int n = sn * 48 + mi * 16 + g + rr * 8;
                        const int m = sm * 48 + nj * 8 + 2 * l4;
                        if (n < 82 && m < 82) {
                            float2 v = *(float2*)(Sf + n * SP + m);
                            v.x += sc[mi][nj][rr * 2];
                            v.y += sc[mi][nj][rr * 2 + 1];
                            *(float2*)(Sf + n * SP + m) = v;
                        }
                    }
        }
    }
    __syncthreads();

    // ---- softmax: warp per row ----
    for (int r = warp; r < NN; r += 8) {
        float* row = Sf + r * SP;
        float mx = -1e30f;
        for (int m = lane; m < NN; m += 32) mx = fmaxf(mx, row[m]);
#pragma unroll
        for (int s = 16; s > 0; s >>= 1)
            mx = fmaxf(mx, __shfl_xor_sync(0xFFFFFFFF, mx, s));
        float sum = 0.0f;
        for (int m = lane; m < NN; m += 32) {
            float e = __expf(row[m] - mx);
            row[m] = e;
            sum += e;
        }
#pragma unroll
        for (int s = 16; s > 0; s >>= 1)
            sum += __shfl_xor_sync(0xFFFFFFFF, sum, s);
        float inv = 1.0f / sum;
        for (int m = lane; m < NN; m += 32) row[m] *= inv;
    }
    __syncthreads();

    // ---- split P -> fp16 hi/lo planes [n][m], zero outside 81x81 ----
    for (int idx = tid; idx < 96 * 48; idx += 256) {
        const int n  = idx / 48;
        const int mp = idx - n * 48;
        const int m0 = 2 * mp;
        float f0 = (n < NN && m0 < NN)     ? Sf[n * SP + m0]     : 0.0f;
        float f1 = (n < NN && m0 + 1 < NN) ? Sf[n * SP + m0 + 1] : 0.0f;
        split_store(smem, OFF_PH, OFF_PL, n * VSTRIDE + 2 * m0, f0, f1);
    }
    __syncthreads();

    // ================= Phase 3: O = P.V (3-term fp16) =================
    {
        const int pn = warp & 1;          // n half (48)
        const int pd = (warp >> 1) & 1;   // d half (32)
        const int pk = warp >> 2;         // k half (m 48)
        float ov[3][4][4];
#pragma unroll
        for (int i = 0; i < 3; i++)
#pragma unroll
            for (int j = 0; j < 4; j++)
#pragma unroll
                for (int r = 0; r < 4; r++) ov[i][j][r] = 0.0f;

#pragma unroll
        for (int t = 0; t < 3; t++) {
            const uint32_t Ap = sb + ((t < 2) ? OFF_PH : OFF_PL);
            const uint32_t Bp = sb + ((t == 1) ? R0_VL : R0_VH);
#pragma unroll
            for (int ks = 0; ks < 3; ks++) {
                const uint32_t kb = pk * 96 + ks * 32;
                uint32_t a[3][4];
#pragma unroll
                for (int mi = 0; mi < 3; mi++)
                    LDSM4(a[mi][0], a[mi][1], a[mi][2], a[mi][3],
                          Ap + (uint32_t)((pn * 48 + mi * 16) * VSTRIDE) + kb + aoff208);
                uint32_t bv2[2][4];
#pragma unroll
                for (int pr = 0; pr < 2; pr++)
                    LDSM4(bv2[pr][0], bv2[pr][1], bv2[pr][2], bv2[pr][3],
                          Bp + (uint32_t)((pd * 32 + pr * 16) * VSTRIDE) + kb + boff208);
#pragma unroll
                for (int pr = 0; pr < 2; pr++)
#pragma unroll
                    for (int sub = 0; sub < 2; sub++)
#pragma unroll
                        for (int mi = 0; mi < 3; mi++)
                            MMA_F16(ov[mi][pr * 2 + sub], a[mi], bv2[pr] + 2 * sub);
            }
        }
        __syncthreads();   // S dead -> O region reuse safe
        if (pk == 0) {
#pragma unroll
            for (int mi = 0; mi < 3; mi++)
#pragma unroll
                for (int nj = 0; nj < 4; nj++)
#pragma unroll
                    for (int rr = 0; rr < 2; rr++) {
                        const int n = pn * 48 + mi * 16 + g + rr * 8;
                        const int d = pd * 32 + nj * 8 + 2 * l4;
                        if (n < NN)
                            *(float2*)(Of + n * OSTRIDE + d) =
                                make_float2(ov[mi][nj][rr * 2], ov[mi][nj][rr * 2 + 1]);
                    }
        }
        __syncthreads();
        if (pk == 1) {
#pragma unroll
            for (int mi = 0; mi < 3; mi++)
#pragma unroll
                for (int nj = 0; nj < 4; nj++)
#pragma unroll
                    for (int rr = 0; rr < 2; rr++) {
                        const int n = pn * 48 + mi * 16 + g + rr * 8;
                        const int d = pd * 32 + nj * 8 + 2 * l4;
                        if (n < NN) {
                            float2 v = *(float2*)(Of + n * OSTRIDE + d);
                            float o0 = v.x + ov[mi][nj][rr * 2];
                            float o1 = v.y + ov[mi][nj][rr * 2 + 1];
                            float* dst = out + ((size_t)b * DM + h64 + d) * NN + n;
                            dst[0]  = o0;
                            dst[NN] = o1;
                        }
                    }
        }
    }
}

// ---------------------------------------------------------------------------
extern "C" void kernel_launch(void* const* d_in, const int* in_sizes, int n_in,
                              void* d_out, int out_size) {
    const float* x     = (const float*)d_in[0];
    const float* qkv_w = (const float*)d_in[1];
    const float* qkv_b = (const float*)d_in[2];
    const float* rel_h = (const float*)d_in[3];
    const float* rel_w = (const float*)d_in[4];
    float* out = (float*)d_out;

    cudaFuncSetAttribute(fused_mhsa, cudaFuncAttributeMaxDynamicSharedMemorySize, SMEM_FUSED);

    prep_w<<<OC * DM / 256, 256>>>(qkv_w);
    prep_x<<<dim3(BB, DM / 64), 256>>>(x);
    fused_mhsa<<<BB * NH, 256, SMEM_FUSED>>>(qkv_b, rel_h, rel_w, out);
}

// round 12
// speedup vs baseline: 1.6477x; 1.0331x over previous
#include <cuda_runtime.h>
#include <cuda_fp16.h>
#include <math.h>
#include <stdint.h>

// Problem constants
#define BB   1024
#define DM   512
#define NH   8
#define HD   64
#define NN   81
#define OC   1536

// Phase-1 GEMM staging
#define KT     32
#define NTILES (DM / KT)     // 16
#define RSTRIDE 80           // 64B data + 16B pad
#define WROWS  192
#define XROWS  96
#define WTILE  (WROWS * RSTRIDE)        // 15360
#define XTILE  (XROWS * RSTRIDE)        // 7680
#define STG_BYTES (WTILE + XTILE)       // 23040
#define STAGES    (2 * STG_BYTES)       // 46080

// fp16 hi/lo planes
#define QKSTRIDE 144         // Q/K: 96 rows x (128B data + 16 pad)
#define VSTRIDE  208         // V: 64 rows, P: 96 rows x (192B data + 16 pad)
#define QKPLANE  (96 * QKSTRIDE)        // 13824
#define VPLANE   (64 * VSTRIDE)         // 13312

#define SP       84          // S row stride (floats)
#define OSTRIDE  68          // O-combine row stride (floats)

// smem map
#define R0_VH   0
#define R0_VL   VPLANE
#define R0_S    (2 * VPLANE)                 // 26624 (stages dead by then)
#define R0_O    R0_S
#define R0_SIZE (R0_S + 82 * SP * 4)         // 54176
#define OFF_QH  (R0_SIZE)
#define OFF_QL  (R0_SIZE + QKPLANE)
#define OFF_KH  (R0_SIZE + 2 * QKPLANE)
#define OFF_KL  (R0_SIZE + 3 * QKPLANE)
#define OFF_PH  (R0_SIZE)                    // P (hi only) overlays Q after scores
#define SMEM_FUSED (R0_SIZE + 4 * QKPLANE)   // 109472 -> 2 CTAs/SM

// Scratch (fp16 inputs only)
__device__ __half g_wh[(size_t)OC * DM];
__device__ __half g_xh[(size_t)BB * 96 * DM];

__device__ __forceinline__ uint32_t smem_u32(const void* p) {
    uint32_t a;
    asm("{ .reg .u64 t; cvta.to.shared.u64 t, %1; cvt.u32.u64 %0, t; }" : "=r"(a) : "l"(p));
    return a;
}

#define CP16(dst, src) \
    asm volatile("cp.async.cg.shared.global [%0], [%1], 16;" :: "r"(dst), "l"(src))
#define CP_COMMIT() asm volatile("cp.async.commit_group;" ::: "memory")
#define CP_WAIT(n)  asm volatile("cp.async.wait_group %0;" :: "n"(n) : "memory")

#define LDSM4(r0, r1, r2, r3, addr)                                           \
    asm volatile("ldmatrix.sync.aligned.m8n8.x4.shared.b16 {%0,%1,%2,%3}, [%4];" \
        : "=r"(r0), "=r"(r1), "=r"(r2), "=r"(r3) : "r"(addr))

#define LDSM2(r0, r1, addr)                                                   \
    asm volatile("ldmatrix.sync.aligned.m8n8.x2.shared.b16 {%0,%1}, [%2];"    \
        : "=r"(r0), "=r"(r1) : "r"(addr))

#define MMA_F16(C, A, B)                                                      \
    asm volatile(                                                             \
        "mma.sync.aligned.m16n8k16.row.col.f32.f16.f16.f32 "                  \
        "{%0,%1,%2,%3}, {%4,%5,%6,%7}, {%8,%9}, {%0,%1,%2,%3};\n"             \
        : "+f"((C)[0]), "+f"((C)[1]), "+f"((C)[2]), "+f"((C)[3])              \
        : "r"((A)[0]), "r"((A)[1]), "r"((A)[2]), "r"((A)[3]),                 \
          "r"((B)[0]), "r"((B)[1]))

// split v into fp16 hi + lo, store half2-packed pair to hi/lo planes
__device__ __forceinline__ void split_store(char* smem, int offH, int offL,
                                            int byteoff, float v0, float v1) {
    __half h0 = __float2half_rn(v0);
    __half h1 = __float2half_rn(v1);
    float  l0 = v0 - __half2float(h0);
    float  l1 = v1 - __half2float(h1);
    *(__half2*)(smem + offH + byteoff) = __halves2half2(h0, h1);
    *(__half2*)(smem + offL + byteoff) =
        __halves2half2(__float2half_rn(l0), __float2half_rn(l1));
}

// ---------------------------------------------------------------------------
__global__ void prep_w(const float* __restrict__ w) {
    int i = blockIdx.x * 256 + threadIdx.x;
    g_wh[i] = __float2half_rn(w[i]);
}

__global__ __launch_bounds__(256) void prep_x(const float* __restrict__ x) {
    __shared__ float ts[64][83];
    const int b  = blockIdx.x;
    const int c0 = blockIdx.y * 64;
    const int tid = threadIdx.x;

    const float* xb = x + ((size_t)b * DM + c0) * NN;
    for (int idx = tid; idx < 64 * NN; idx += 256) {
        int c = idx / NN;
        int n = idx - c * NN;
        ts[c][n] = xb[(size_t)c * NN + n];
    }
    __syncthreads();

    for (int idx = tid; idx < 96 * 64; idx += 256) {
        int n = idx >> 6;
        int c = idx & 63;
        float v = (n < NN) ? ts[c][n] : 0.0f;
        g_xh[((size_t)b * 96 + n) * DM + c0 + c] = __float2half_rn(v);
    }
}

// ---------------------------------------------------------------------------
// Stage loader: W rows (Q|K|V for head h) + X rows for batch b
// ---------------------------------------------------------------------------
__device__ __forceinline__ void load_stage(uint32_t sb, int stage,
                                           int k0, int h64, int b, int tid) {
    const uint32_t base = sb + stage * STG_BYTES;
#pragma unroll
    for (int i = 0; i < 3; i++) {                // W: 768 chunks
        int idx = tid + i * 256;
        int row = idx >> 2;
        int chv = idx & 3;
        int o   = (row >> 6) * DM + h64 + (row & 63);
        const __half* src = g_wh + (size_t)o * DM + k0 + chv * 8;
        CP16(base + row * RSTRIDE + chv * 16, src);
    }
#pragma unroll
    for (int i = 0; i < 2; i++) {                // X: 384 chunks
        int idx = tid + i * 256;
        if (idx < 384) {
            int row = idx >> 2;
            int chv = idx & 3;
            const __half* src = g_xh + ((size_t)b * 96 + row) * DM + k0 + chv * 8;
            CP16(base + WTILE + row * RSTRIDE + chv * 16, src);
        }
    }
    CP_COMMIT();
}

// ---------------------------------------------------------------------------
// Fused kernel: QKV GEMM + scores (3-term) + softmax + PV (2-term), fp16 HMMA
// ---------------------------------------------------------------------------
__global__ __launch_bounds__(256, 2) void fused_mhsa(const float* __restrict__ bias,
                                                     const float* __restrict__ rel_h,
                                                     const float* __restrict__ rel_w,
                                                     float* __restrict__ out) {
    extern __shared__ char smem[];
    const uint32_t sb = smem_u32(smem);
    float* Sf = (float*)(smem + R0_S);
    float* Of = (float*)(smem + R0_O);

    const int tid  = threadIdx.x;
    const int bh   = blockIdx.x;
    const int b    = bh >> 3;
    const int h64  = (bh & 7) * HD;
    const int warp = tid >> 5;
    const int lane = tid & 31;
    const int g    = lane >> 2;
    const int l4   = lane & 3;

    const uint32_t arow = (lane & 7) + ((lane >> 3) & 1) * 8;
    const uint32_t acol = (lane >> 4) * 16;
    const uint32_t brow = (lane & 7) + ((lane >> 4) & 1) * 8;
    const uint32_t bcol = ((lane >> 3) & 1) * 16;
    const uint32_t aoff80  = arow * 80  + acol;
    const uint32_t boff80  = brow * 80  + bcol;
    const uint32_t aoff144 = arow * 144 + acol;
    const uint32_t boff144 = brow * 144 + bcol;
    const uint32_t aoff208 = arow * 208 + acol;
    const uint32_t boff208 = brow * 208 + bcol;

    // ================= Phase 1: QKV projection =================
    const int wA = warp & 1;    // M half
    const int wB = warp >> 1;   // N quarter (0..3)

    float qk[3][4][4];
    float vv[2][3][4];
#pragma unroll
    for (int i = 0; i < 3; i++)
#pragma unroll
        for (int j = 0; j < 4; j++)
#pragma unroll
            for (int r = 0; r < 4; r++) qk[i][j][r] = 0.0f;
#pragma unroll
    for (int i = 0; i < 2; i++)
#pragma unroll
        for (int j = 0; j < 3; j++)
#pragma unroll
            for (int r = 0; r < 4; r++) vv[i][j][r] = 0.0f;

    load_stage(sb, 0, 0, h64, b, tid);
    load_stage(sb, 1, KT, h64, b, tid);

    for (int ch = 0; ch < NTILES; ch++) {
        if (ch + 1 < NTILES) { CP_WAIT(1); } else { CP_WAIT(0); }
        __syncthreads();

        const uint32_t Wt = sb + (ch & 1) * STG_BYTES;
        const uint32_t Xt = Wt + WTILE;

#pragma unroll
        for (int ks = 0; ks < 2; ks++) {
            const uint32_t kb = ks * 32;
            // --- QK ---
            uint32_t a[3][4];
#pragma unroll
            for (int mi = 0; mi < 3; mi++)
                LDSM4(a[mi][0], a[mi][1], a[mi][2], a[mi][3],
                      Xt + (uint32_t)((wA * 48 + mi * 16) * 80) + kb + aoff80);
            uint32_t bw[2][4];
#pragma unroll
            for (int pr = 0; pr < 2; pr++)
                LDSM4(bw[pr][0], bw[pr][1], bw[pr][2], bw[pr][3],
                      Wt + (uint32_t)((wB * 32 + pr * 16) * 80) + kb + boff80);
#pragma unroll
            for (int pr = 0; pr < 2; pr++)
#pragma unroll
                for (int sub = 0; sub < 2; sub++)
#pragma unroll
                    for (int mi = 0; mi < 3; mi++)
                        MMA_F16(qk[mi][pr * 2 + sub], a[mi], bw[pr] + 2 * sub);
            // --- V ---
            uint32_t av[2][4];
#pragma unroll
            for (int mi = 0; mi < 2; mi++)
                LDSM4(av[mi][0], av[mi][1], av[mi][2], av[mi][3],
                      Wt + (uint32_t)((128 + wA * 32 + mi * 16) * 80) + kb + aoff80);
            uint32_t bx0[4], bx2[2];
            LDSM4(bx0[0], bx0[1], bx0[2], bx0[3],
                  Xt + (uint32_t)((wB * 24) * 80) + kb + boff80);
            LDSM2(bx2[0], bx2[1],
                  Xt + (uint32_t)((wB * 24 + 16 + (lane & 7)) * 80) + kb
                     + ((lane >> 3) & 1) * 16);
#pragma unroll
            for (int mi = 0; mi < 2; mi++) {
                MMA_F16(vv[mi][0], av[mi], bx0 + 0);
                MMA_F16(vv[mi][1], av[mi], bx0 + 2);
                MMA_F16(vv[mi][2], av[mi], bx2);
            }
        }

        if (ch + 2 < NTILES) {
            __syncthreads();
            load_stage(sb, ch & 1, (ch + 2) * KT, h64, b, tid);
        }
    }
    __syncthreads();   // stages dead; V epilogue reuses that space

    // ---- Epilogue 1a: Q/K accums -> fp16 hi/lo planes [token][d] ----
#pragma unroll
    for (int mi = 0; mi < 3; mi++) {
#pragma unroll
        for (int rr = 0; rr < 2; rr++) {
            const int tok = wA * 48 + mi * 16 + g + rr * 8;
            const int tc  = (tok < NN) ? tok : 80;
#pragma unroll
            for (int ni = 0; ni < 4; ni++) {
                const int o  = wB * 32 + ni * 8 + 2 * l4;
                float c0 = qk[mi][ni][rr * 2 + 0];
                float c1 = qk[mi][ni][rr * 2 + 1];
                if (wB < 2) {          // Q
                    c0 += bias[h64 + o];
                    c1 += bias[h64 + o + 1];
                    split_store(smem, OFF_QH, OFF_QL, tok * QKSTRIDE + 2 * o, c0, c1);
                } else {               // K (+rel fold)
                    const int d = o - 64;
                    c0 += bias[512 + h64 + d]
                        + rel_h[(h64 + d) * 9 + tc % 9] + rel_w[(h64 + d) * 9 + tc / 9];
                    c1 += bias[512 + h64 + d + 1]
                        + rel_h[(h64 + d + 1) * 9 + tc % 9] + rel_w[(h64 + d + 1) * 9 + tc / 9];
                    split_store(smem, OFF_KH, OFF_KL, tok * QKSTRIDE + 2 * d, c0, c1);
                }
            }
        }
    }
    // ---- Epilogue 1b: V accums -> fp16 hi/lo planes [d][token] ----
#pragma unroll
    for (int mi = 0; mi < 2; mi++) {
#pragma unroll
        for (int rr = 0; rr < 2; rr++) {
            const int d  = wA * 32 + mi * 16 + g + rr * 8;
            const float bv = bias[1024 + h64 + d];
#pragma unroll
            for (int ni = 0; ni < 3; ni++) {
                const int tok = wB * 24 + ni * 8 + 2 * l4;
                split_store(smem, R0_VH, R0_VL, d * VSTRIDE + 2 * tok,
                            vv[mi][ni][rr * 2] + bv, vv[mi][ni][rr * 2 + 1] + bv);
            }
        }
    }
    __syncthreads();

    // ================= Phase 2: S = Q.K^T (3-term, A-frag reuse) ===========
    {
        const int sn = warp & 1;          // n half (48)
        const int sm = (warp >> 1) & 1;   // m half (48)
        const int sk = warp >> 2;         // k half (d 32)
        float sc[3][6][4];
#pragma unroll
        for (int i = 0; i < 3; i++)
#pragma unroll
            for (int j = 0; j < 6; j++)
#pragma unroll
                for (int r = 0; r < 4; r++) sc[i][j][r] = 0.0f;

#pragma unroll
        for (int ks = 0; ks < 2; ks++) {
            const uint32_t kb = sk * 64 + ks * 32;
            uint32_t ah[3][4], al[3][4];
#pragma unroll
            for (int mi = 0; mi < 3; mi++) {
                const uint32_t ro = (uint32_t)((sn * 48 + mi * 16) * QKSTRIDE) + kb + aoff144;
                LDSM4(ah[mi][0], ah[mi][1], ah[mi][2], ah[mi][3], sb + OFF_QH + ro);
                LDSM4(al[mi][0], al[mi][1], al[mi][2], al[mi][3], sb + OFF_QL + ro);
            }
#pragma unroll
            for (int pr = 0; pr < 3; pr++) {
                const uint32_t rb = (uint32_t)((sm * 48 + pr * 16) * QKSTRIDE) + kb + boff144;
                uint32_t bk[4];
                LDSM4(bk[0], bk[1], bk[2], bk[3], sb + OFF_KH + rb);
#pragma unroll
                for (int sub = 0; sub < 2; sub++)
#pragma unroll
                    for (int mi = 0; mi < 3; mi++) {
                        MMA_F16(sc[mi][pr * 2 + sub], ah[mi], bk + 2 * sub);  // hi*hi
                        MMA_F16(sc[mi][pr * 2 + sub], al[mi], bk + 2 * sub);  // lo*hi
                    }
                LDSM4(bk[0], bk[1], bk[2], bk[3], sb + OFF_KL + rb);
#pragma unroll
                for (int sub = 0; sub < 2; sub++)
#pragma unroll
                    for (int mi = 0; mi < 3; mi++)
                        MMA_F16(sc[mi][pr * 2 + sub], ah[mi], bk + 2 * sub);  // hi*lo
            }
        }
        // combine k-halves into S (two passes)
        if (sk == 0) {
#pragma unroll
            for (int mi = 0; mi < 3; mi++)
#pragma unroll
                for (int nj = 0; nj < 6; nj++)
#pragma unroll
                    for (int rr = 0; rr < 2; rr++) {
                        const int n = sn * 48 + mi * 16 + g + rr * 8;
                        const int m = sm * 48 + nj * 8 + 2 * l4;
                        if (n < 82 && m < 82)
                            *(float2*)(Sf + n * SP + m) =
                                make_float2(sc[mi][nj][rr * 2], sc[mi][nj][rr * 2 + 1]);
                    }
        }
        __syncthreads();
        if (sk == 1) {
#pragma unroll
            for (int mi = 0; mi < 3; mi++)
#pragma unroll
                for (int nj = 0; nj < 6; nj++)
#pragma unroll
                    for (int rr = 0; rr < 2; rr++) {
                        const int n = sn * 48 + mi * 16 + g + rr * 8;
                        const int m = sm * 48 + nj * 8 + 2 * l4;
                        if (n < 82 && m < 82) {
                            float2 v = *(float2*)(Sf + n * SP + m);
                            v.x += sc[mi][nj][rr * 2];
                            v.y += sc[mi][nj][rr * 2 + 1];
                            *(float2*)(Sf + n * SP + m) = v;
                        }
                    }
        }
    }
    __syncthreads();

    // ---- softmax (warp per row) fused with Ph fp16 write + zero-pad cols ----
    for (int r = warp; r < NN; r += 8) {
        float* row = Sf + r * SP;
        float mx = -1e30f;
        for (int m = lane; m < NN; m += 32) mx = fmaxf(mx, row[m]);
#pragma unroll
        for (int s = 16; s > 0; s >>= 1)
            mx = fmaxf(mx, __shfl_xor_sync(0xFFFFFFFF, mx, s));
        float sum = 0.0f;
        for (int m = lane; m < NN; m += 32) {
            float e = __expf(row[m] - mx);
            row[m] = e;
            sum += e;
        }
#pragma unroll
        for (int s = 16; s > 0; s >>= 1)
            sum += __shfl_xor_sync(0xFFFFFFFF, sum, s);
        float inv = 1.0f / sum;
        for (int m = lane; m < 96; m += 32) {
            float v = (m < NN) ? row[m] * inv : 0.0f;
            *(__half*)(smem + OFF_PH + r * VSTRIDE + 2 * m) = __float2half_rn(v);
        }
    }
    __syncthreads();

    // ================= Phase 3: O = P.V (2-term: Ph*Vh + Ph*Vl) ============
    {
        const int pn = warp & 1;          // n half (48)
        const int pd = (warp >> 1) & 1;   // d half (32)
        const int pk = warp >> 2;         // k half (m 48)
        float ov[3][4][4];
#pragma unroll
        for (int i = 0; i < 3; i++)
#pragma unroll
            for (int j = 0; j < 4; j++)
#pragma unroll
                for (int r = 0; r < 4; r++) ov[i][j][r] = 0.0f;

#pragma unroll
        for (int ks = 0; ks < 3; ks++) {
            const uint32_t kb = pk * 96 + ks * 32;
            uint32_t a[3][4];
#pragma unroll
            for (int mi = 0; mi < 3; mi++)
                LDSM4(a[mi][0], a[mi][1], a[mi][2], a[mi][3],
                      sb + OFF_PH + (uint32_t)((pn * 48 + mi * 16) * VSTRIDE) + kb + aoff208);
#pragma unroll
            for (int pr = 0; pr < 2; pr++) {
                const uint32_t rb = (uint32_t)((pd * 32 + pr * 16) * VSTRIDE) + kb + boff208;
                uint32_t bv2[4];
                LDSM4(bv2[0], bv2[1], bv2[2], bv2[3], sb + R0_VH + rb);
#pragma unroll
                for (int sub = 0; sub < 2; sub++)
#pragma unroll
                    for (int mi = 0; mi < 3; mi++)
                        MMA_F16(ov[mi][pr * 2 + sub], a[mi], bv2 + 2 * sub);  // Ph*Vh
                LDSM4(bv2[0], bv2[1], bv2[2], bv2[3], sb + R0_VL + rb);
#pragma unroll
                for (int sub = 0; sub < 2; sub++)
#pragma unroll
                    for (int mi = 0; mi < 3; mi++)
                        MMA_F16(ov[mi][pr * 2 + sub], a[mi], bv2 + 2 * sub);  // Ph*Vl
            }
        }
        __syncthreads();   // S dead -> O region reuse safe
        if (pk == 0) {
#pragma unroll
            for (int mi = 0; mi < 3; mi++)
#pragma unroll
                for (int nj = 0; nj < 4; nj++)
#pragma unroll
                    for (int rr = 0; rr < 2; rr++) {
                        const int n = pn * 48 + mi * 16 + g + rr * 8;
                        const int d = pd * 32 + nj * 8 + 2 * l4;
                        if (n < NN)
                            *(float2*)(Of + n * OSTRIDE + d) =
                                make_float2(ov[mi][nj][rr * 2], ov[mi][nj][rr * 2 + 1]);
                    }
        }
        __syncthreads();
        if (pk == 1) {
#pragma unroll
            for (int mi = 0; mi < 3; mi++)
#pragma unroll
                for (int nj = 0; nj < 4; nj++)
#pragma unroll
                    for (int rr = 0; rr < 2; rr++) {
                        const int n = pn * 48 + mi * 16 + g + rr * 8;
                        const int d = pd * 32 + nj * 8 + 2 * l4;
                        if (n < NN) {
                            float2 v = *(float2*)(Of + n * OSTRIDE + d);
                            float o0 = v.x + ov[mi][nj][rr * 2];
                            float o1 = v.y + ov[mi][nj][rr * 2 + 1];
                            float* dst = out + ((size_t)b * DM + h64 + d) * NN + n;
                            dst[0]  = o0;
                            dst[NN] = o1;
                        }
                    }
        }
    }
}

// ---------------------------------------------------------------------------
extern "C" void kernel_launch(void* const* d_in, const int* in_sizes, int n_in,
                              void* d_out, int out_size) {
    const float* x     = (const float*)d_in[0];
    const float* qkv_w = (const float*)d_in[1];
    const float* qkv_b = (const float*)d_in[2];
    const float* rel_h = (const float*)d_in[3];
    const float* rel_w = (const float*)d_in[4];
    float* out = (float*)d_out;

    cudaFuncSetAttribute(fused_mhsa, cudaFuncAttributeMaxDynamicSharedMemorySize, SMEM_FUSED);

    prep_w<<<OC * DM / 256, 256>>>(qkv_w);
    prep_x<<<dim3(BB, DM / 64), 256>>>(x);
    fused_mhsa<<<BB * NH, 256, SMEM_FUSED>>>(qkv_b, rel_h, rel_w, out);
}

// round 13
// speedup vs baseline: 1.6844x; 1.0223x over previous
#include <cuda_runtime.h>
#include <cuda_fp16.h>
#include <math.h>
#include <stdint.h>

// Problem constants
#define BB   1024
#define DM   512
#define NH   8
#define HD   64
#define NN   81
#define OC   1536

// Phase-1 GEMM staging
#define KT     32
#define NTILES (DM / KT)     // 16
#define RSTRIDE 80           // 64B data + 16B pad
#define WROWS  192
#define XROWS  96
#define WTILE  (WROWS * RSTRIDE)        // 15360
#define XTILE  (XROWS * RSTRIDE)        // 7680
#define STG_BYTES (WTILE + XTILE)       // 23040
#define STAGES    (2 * STG_BYTES)       // 46080

// fp16 planes
#define QKSTRIDE 144         // Q/K: 96 rows x (128B data + 16 pad)
#define VSTRIDE  208         // V: 64 rows, P: 96 rows x (192B data + 16 pad)
#define QKPLANE  (96 * QKSTRIDE)        // 13824
#define VPLANE   (64 * VSTRIDE)         // 13312

#define SP       84          // S row stride (floats)
#define OSTRIDE  68          // O-combine row stride (floats)

// smem map
#define R0_VH   0
#define R0_VL   VPLANE
#define R0_S    (2 * VPLANE)                 // 26624 (stages dead by then)
#define R0_O    R0_S
#define R0_SIZE (R0_S + 82 * SP * 4)         // 54176
#define OFF_QH  (R0_SIZE)                    // Q hi only (no lo plane)
#define OFF_KH  (R0_SIZE + QKPLANE)
#define OFF_KL  (R0_SIZE + 2 * QKPLANE)
#define OFF_PH  (R0_SIZE)                    // P overlays Q (+dead K-hi) after scores
#define SMEM_FUSED (R0_SIZE + 3 * QKPLANE)   // 95648 -> 2 CTAs/SM

// Scratch (fp16 inputs only)
__device__ __half g_wh[(size_t)OC * DM];
__device__ __half g_xh[(size_t)BB * 96 * DM];

__device__ __forceinline__ uint32_t smem_u32(const void* p) {
    uint32_t a;
    asm("{ .reg .u64 t; cvta.to.shared.u64 t, %1; cvt.u32.u64 %0, t; }" : "=r"(a) : "l"(p));
    return a;
}

#define CP16(dst, src) \
    asm volatile("cp.async.cg.shared.global [%0], [%1], 16;" :: "r"(dst), "l"(src))
#define CP_COMMIT() asm volatile("cp.async.commit_group;" ::: "memory")
#define CP_WAIT(n)  asm volatile("cp.async.wait_group %0;" :: "n"(n) : "memory")

#define LDSM4(r0, r1, r2, r3, addr)                                           \
    asm volatile("ldmatrix.sync.aligned.m8n8.x4.shared.b16 {%0,%1,%2,%3}, [%4];" \
        : "=r"(r0), "=r"(r1), "=r"(r2), "=r"(r3) : "r"(addr))

#define LDSM2(r0, r1, addr)                                                   \
    asm volatile("ldmatrix.sync.aligned.m8n8.x2.shared.b16 {%0,%1}, [%2];"    \
        : "=r"(r0), "=r"(r1) : "r"(addr))

#define MMA_F16(C, A, B)                                                      \
    asm volatile(                                                             \
        "mma.sync.aligned.m16n8k16.row.col.f32.f16.f16.f32 "                  \
        "{%0,%1,%2,%3}, {%4,%5,%6,%7}, {%8,%9}, {%0,%1,%2,%3};\n"             \
        : "+f"((C)[0]), "+f"((C)[1]), "+f"((C)[2]), "+f"((C)[3])              \
        : "r"((A)[0]), "r"((A)[1]), "r"((A)[2]), "r"((A)[3]),                 \
          "r"((B)[0]), "r"((B)[1]))

// split v into fp16 hi + lo, store half2-packed pair to hi/lo planes
__device__ __forceinline__ void split_store(char* smem, int offH, int offL,
                                            int byteoff, float v0, float v1) {
    __half h0 = __float2half_rn(v0);
    __half h1 = __float2half_rn(v1);
    float  l0 = v0 - __half2float(h0);
    float  l1 = v1 - __half2float(h1);
    *(__half2*)(smem + offH + byteoff) = __halves2half2(h0, h1);
    *(__half2*)(smem + offL + byteoff) =
        __halves2half2(__float2half_rn(l0), __float2half_rn(l1));
}

// ---------------------------------------------------------------------------
__global__ void prep_w(const float* __restrict__ w) {
    int i = blockIdx.x * 256 + threadIdx.x;
    g_wh[i] = __float2half_rn(w[i]);
}

__global__ __launch_bounds__(256) void prep_x(const float* __restrict__ x) {
    __shared__ float ts[64][83];
    const int b  = blockIdx.x;
    const int c0 = blockIdx.y * 64;
    const int tid = threadIdx.x;

    const float* xb = x + ((size_t)b * DM + c0) * NN;
    for (int idx = tid; idx < 64 * NN; idx += 256) {
        int c = idx / NN;
        int n = idx - c * NN;
        ts[c][n] = xb[(size_t)c * NN + n];
    }
    __syncthreads();

    for (int idx = tid; idx < 96 * 64; idx += 256) {
        int n = idx >> 6;
        int c = idx & 63;
        float v = (n < NN) ? ts[c][n] : 0.0f;
        g_xh[((size_t)b * 96 + n) * DM + c0 + c] = __float2half_rn(v);
    }
}

// ---------------------------------------------------------------------------
// Stage loader: W rows (Q|K|V for head h) + X rows for batch b
// ---------------------------------------------------------------------------
__device__ __forceinline__ void load_stage(uint32_t sb, int stage,
                                           int k0, int h64, int b, int tid) {
    const uint32_t base = sb + stage * STG_BYTES;
#pragma unroll
    for (int i = 0; i < 3; i++) {                // W: 768 chunks
        int idx = tid + i * 256;
        int row = idx >> 2;
        int chv = idx & 3;
        int o   = (row >> 6) * DM + h64 + (row & 63);
        const __half* src = g_wh + (size_t)o * DM + k0 + chv * 8;
        CP16(base + row * RSTRIDE + chv * 16, src);
    }
#pragma unroll
    for (int i = 0; i < 2; i++) {                // X: 384 chunks
        int idx = tid + i * 256;
        if (idx < 384) {
            int row = idx >> 2;
            int chv = idx & 3;
            const __half* src = g_xh + ((size_t)b * 96 + row) * DM + k0 + chv * 8;
            CP16(base + WTILE + row * RSTRIDE + chv * 16, src);
        }
    }
    CP_COMMIT();
}

// ---------------------------------------------------------------------------
// Fused kernel: QKV GEMM + scores (2-term Qh*K) + softmax + PV (2-term Ph*V)
// ---------------------------------------------------------------------------
__global__ __launch_bounds__(256, 2) void fused_mhsa(const float* __restrict__ bias,
                                                     const float* __restrict__ rel_h,
                                                     const float* __restrict__ rel_w,
                                                     float* __restrict__ out) {
    extern __shared__ char smem[];
    const uint32_t sb = smem_u32(smem);
    float* Sf = (float*)(smem + R0_S);
    float* Of = (float*)(smem + R0_O);

    const int tid  = threadIdx.x;
    const int bh   = blockIdx.x;
    const int b    = bh >> 3;
    const int h64  = (bh & 7) * HD;
    const int warp = tid >> 5;
    const int lane = tid & 31;
    const int g    = lane >> 2;
    const int l4   = lane & 3;

    const uint32_t arow = (lane & 7) + ((lane >> 3) & 1) * 8;
    const uint32_t acol = (lane >> 4) * 16;
    const uint32_t brow = (lane & 7) + ((lane >> 4) & 1) * 8;
    const uint32_t bcol = ((lane >> 3) & 1) * 16;
    const uint32_t aoff80  = arow * 80  + acol;
    const uint32_t boff80  = brow * 80  + bcol;
    const uint32_t aoff144 = arow * 144 + acol;
    const uint32_t boff144 = brow * 144 + bcol;
    const uint32_t aoff208 = arow * 208 + acol;
    const uint32_t boff208 = brow * 208 + bcol;

    // ================= Phase 1: QKV projection =================
    const int wA = warp & 1;    // M half
    const int wB = warp >> 1;   // N quarter (0..3)

    float qk[3][4][4];
    float vv[2][3][4];
#pragma unroll
    for (int i = 0; i < 3; i++)
#pragma unroll
        for (int j = 0; j < 4; j++)
#pragma unroll
            for (int r = 0; r < 4; r++) qk[i][j][r] = 0.0f;
#pragma unroll
    for (int i = 0; i < 2; i++)
#pragma unroll
        for (int j = 0; j < 3; j++)
#pragma unroll
            for (int r = 0; r < 4; r++) vv[i][j][r] = 0.0f;

    load_stage(sb, 0, 0, h64, b, tid);
    load_stage(sb, 1, KT, h64, b, tid);

    for (int ch = 0; ch < NTILES; ch++) {
        if (ch + 1 < NTILES) { CP_WAIT(1); } else { CP_WAIT(0); }
        __syncthreads();

        const uint32_t Wt = sb + (ch & 1) * STG_BYTES;
        const uint32_t Xt = Wt + WTILE;

#pragma unroll
        for (int ks = 0; ks < 2; ks++) {
            const uint32_t kb = ks * 32;
            // --- QK ---
            uint32_t a[3][4];
#pragma unroll
            for (int mi = 0; mi < 3; mi++)
                LDSM4(a[mi][0], a[mi][1], a[mi][2], a[mi][3],
                      Xt + (uint32_t)((wA * 48 + mi * 16) * 80) + kb + aoff80);
            uint32_t bw[2][4];
#pragma unroll
            for (int pr = 0; pr < 2; pr++)
                LDSM4(bw[pr][0], bw[pr][1], bw[pr][2], bw[pr][3],
                      Wt + (uint32_t)((wB * 32 + pr * 16) * 80) + kb + boff80);
#pragma unroll
            for (int pr = 0; pr < 2; pr++)
#pragma unroll
                for (int sub = 0; sub < 2; sub++)
#pragma unroll
                    for (int mi = 0; mi < 3; mi++)
                        MMA_F16(qk[mi][pr * 2 + sub], a[mi], bw[pr] + 2 * sub);
            // --- V ---
            uint32_t av[2][4];
#pragma unroll
            for (int mi = 0; mi < 2; mi++)
                LDSM4(av[mi][0], av[mi][1], av[mi][2], av[mi][3],
                      Wt + (uint32_t)((128 + wA * 32 + mi * 16) * 80) + kb + aoff80);
            uint32_t bx0[4], bx2[2];
            LDSM4(bx0[0], bx0[1], bx0[2], bx0[3],
                  Xt + (uint32_t)((wB * 24) * 80) + kb + boff80);
            LDSM2(bx2[0], bx2[1],
                  Xt + (uint32_t)((wB * 24 + 16 + (lane & 7)) * 80) + kb
                     + ((lane >> 3) & 1) * 16);
#pragma unroll
            for (int mi = 0; mi < 2; mi++) {
                MMA_F16(vv[mi][0], av[mi], bx0 + 0);
                MMA_F16(vv[mi][1], av[mi], bx0 + 2);
                MMA_F16(vv[mi][2], av[mi], bx2);
            }
        }

        if (ch + 2 < NTILES) {
            __syncthreads();
            load_stage(sb, ch & 1, (ch + 2) * KT, h64, b, tid);
        }
    }
    __syncthreads();   // stages dead; V epilogue reuses that space

    // ---- Epilogue 1a: Q (hi only) / K (hi+lo) -> fp16 planes [token][d] ----
#pragma unroll
    for (int mi = 0; mi < 3; mi++) {
#pragma unroll
        for (int rr = 0; rr < 2; rr++) {
            const int tok = wA * 48 + mi * 16 + g + rr * 8;
            const int tc  = (tok < NN) ? tok : 80;
#pragma unroll
            for (int ni = 0; ni < 4; ni++) {
                const int o  = wB * 32 + ni * 8 + 2 * l4;
                float c0 = qk[mi][ni][rr * 2 + 0];
                float c1 = qk[mi][ni][rr * 2 + 1];
                if (wB < 2) {          // Q: single fp16 plane
                    c0 += bias[h64 + o];
                    c1 += bias[h64 + o + 1];
                    *(__half2*)(smem + OFF_QH + tok * QKSTRIDE + 2 * o) =
                        __halves2half2(__float2half_rn(c0), __float2half_rn(c1));
                } else {               // K (+rel fold): hi/lo split
                    const int d = o - 64;
                    c0 += bias[512 + h64 + d]
                        + rel_h[(h64 + d) * 9 + tc % 9] + rel_w[(h64 + d) * 9 + tc / 9];
                    c1 += bias[512 + h64 + d + 1]
                        + rel_h[(h64 + d + 1) * 9 + tc % 9] + rel_w[(h64 + d + 1) * 9 + tc / 9];
                    split_store(smem, OFF_KH, OFF_KL, tok * QKSTRIDE + 2 * d, c0, c1);
                }
            }
        }
    }
    // ---- Epilogue 1b: V accums -> fp16 hi/lo planes [d][token] ----
#pragma unroll
    for (int mi = 0; mi < 2; mi++) {
#pragma unroll
        for (int rr = 0; rr < 2; rr++) {
            const int d  = wA * 32 + mi * 16 + g + rr * 8;
            const float bv = bias[1024 + h64 + d];
#pragma unroll
            for (int ni = 0; ni < 3; ni++) {
                const int tok = wB * 24 + ni * 8 + 2 * l4;
                split_store(smem, R0_VH, R0_VL, d * VSTRIDE + 2 * tok,
                            vv[mi][ni][rr * 2] + bv, vv[mi][ni][rr * 2 + 1] + bv);
            }
        }
    }
    __syncthreads();

    // ================= Phase 2: S = Qh.(Kh+Kl)^T (2-term) ==================
    {
        const int sn = warp & 1;          // n half (48)
        const int sm = (warp >> 1) & 1;   // m half (48)
        const int sk = warp >> 2;         // k half (d 32)
        float sc[3][6][4];
#pragma unroll
        for (int i = 0; i < 3; i++)
#pragma unroll
            for (int j = 0; j < 6; j++)
#pragma unroll
                for (int r = 0; r < 4; r++) sc[i][j][r] = 0.0f;

#pragma unroll
        for (int ks = 0; ks < 2; ks++) {
            const uint32_t kb = sk * 64 + ks * 32;
            uint32_t ah[3][4];
#pragma unroll
            for (int mi = 0; mi < 3; mi++) {
                const uint32_t ro = (uint32_t)((sn * 48 + mi * 16) * QKSTRIDE) + kb + aoff144;
                LDSM4(ah[mi][0], ah[mi][1], ah[mi][2], ah[mi][3], sb + OFF_QH + ro);
            }
#pragma unroll
            for (int pr = 0; pr < 3; pr++) {
                const uint32_t rb = (uint32_t)((sm * 48 + pr * 16) * QKSTRIDE) + kb + boff144;
                uint32_t bk[4];
                LDSM4(bk[0], bk[1], bk[2], bk[3], sb + OFF_KH + rb);
#pragma unroll
                for (int sub = 0; sub < 2; sub++)
#pragma unroll
                    for (int mi = 0; mi < 3; mi++)
                        MMA_F16(sc[mi][pr * 2 + sub], ah[mi], bk + 2 * sub);  // hi*hi
                LDSM4(bk[0], bk[1], bk[2], bk[3], sb + OFF_KL + rb);
#pragma unroll
                for (int sub = 0; sub < 2; sub++)
#pragma unroll
                    for (int mi = 0; mi < 3; mi++)
                        MMA_F16(sc[mi][pr * 2 + sub], ah[mi], bk + 2 * sub);  // hi*lo
            }
        }
        // combine k-halves into S (two passes)
        if (sk == 0) {
#pragma unroll
            for (int mi = 0; mi < 3; mi++)
#pragma unroll
                for (int nj = 0; nj < 6; nj++)
#pragma unroll
                    for (int rr = 0; rr < 2; rr++) {
                        const int n = sn * 48 + mi * 16 + g + rr * 8;
                        const int m = sm * 48 + nj * 8 + 2 * l4;
                        if (n < 82 && m < 82)
                            *(float2*)(Sf + n * SP + m) =
                                make_float2(sc[mi][nj][rr * 2], sc[mi][nj][rr * 2 + 1]);
                    }
        }
        __syncthreads();
        if (sk == 1) {
#pragma unroll
            for (int mi = 0; mi < 3; mi++)
#pragma unroll
                for (int nj = 0; nj < 6; nj++)
#pragma unroll
                    for (int rr = 0; rr < 2; rr++) {
                        const int n = sn * 48 + mi * 16 + g + rr * 8;
                        const int m = sm * 48 + nj * 8 + 2 * l4;
                        if (n < 82 && m < 82) {
                            float2 v = *(float2*)(Sf + n * SP + m);
                            v.x += sc[mi][nj][rr * 2];
                            v.y += sc[mi][nj][rr * 2 + 1];
                            *(float2*)(Sf + n * SP + m) = v;
                        }
                    }
        }
    }
    __syncthreads();

    // ---- softmax (warp per row) fused with Ph fp16 write + zero-pad cols ----
    for (int r = warp; r < NN; r += 8) {
        float* row = Sf + r * SP;
        float mx = -1e30f;
        for (int m = lane; m < NN; m += 32) mx = fmaxf(mx, row[m]);
#pragma unroll
        for (int s = 16; s > 0; s >>= 1)
            mx = fmaxf(mx, __shfl_xor_sync(0xFFFFFFFF, mx, s));
        float sum = 0.0f;
        for (int m = lane; m < NN; m += 32) {
            float e = __expf(row[m] - mx);
            row[m] = e;
            sum += e;
        }
#pragma unroll
        for (int s = 16; s > 0; s >>= 1)
            sum += __shfl_xor_sync(0xFFFFFFFF, sum, s);
        float inv = 1.0f / sum;
        for (int m = lane; m < 96; m += 32) {
            float v = (m < NN) ? row[m] * inv : 0.0f;
            *(__half*)(smem + OFF_PH + r * VSTRIDE + 2 * m) = __float2half_rn(v);
        }
    }
    __syncthreads();

    // ================= Phase 3: O = P.V (2-term: Ph*Vh + Ph*Vl) ============
    {
        const int pn = warp & 1;          // n half (48)
        const int pd = (warp >> 1) & 1;   // d half (32)
        const int pk = warp >> 2;         // k half (m 48)
        float ov[3][4][4];
#pragma unroll
        for (int i = 0; i < 3; i++)
#pragma unroll
            for (int j = 0; j < 4; j++)
#pragma unroll
                for (int r = 0; r < 4; r++) ov[i][j][r] = 0.0f;

#pragma unroll
        for (int ks = 0; ks < 3; ks++) {
            const uint32_t kb = pk * 96 + ks * 32;
            uint32_t a[3][4];
#pragma unroll
            for (int mi = 0; mi < 3; mi++)
                LDSM4(a[mi][0], a[mi][1], a[mi][2], a[mi][3],
                      sb + OFF_PH + (uint32_t)((pn * 48 + mi * 16) * VSTRIDE) + kb + aoff208);
#pragma unroll
            for (int pr = 0; pr < 2; pr++) {
                const uint32_t rb = (uint32_t)((pd * 32 + pr * 16) * VSTRIDE) + kb + boff208;
                uint32_t bv2[4];
                LDSM4(bv2[0], bv2[1], bv2[2], bv2[3], sb + R0_VH + rb);
#pragma unroll
                for (int sub = 0; sub < 2; sub++)
#pragma unroll
                    for (int mi = 0; mi < 3; mi++)
                        MMA_F16(ov[mi][pr * 2 + sub], a[mi], bv2 + 2 * sub);  // Ph*Vh
                LDSM4(bv2[0], bv2[1], bv2[2], bv2[3], sb + R0_VL + rb);
#pragma unroll
                for (int sub = 0; sub < 2; sub++)
#pragma unroll
                    for (int mi = 0; mi < 3; mi++)
                        MMA_F16(ov[mi][pr * 2 + sub], a[mi], bv2 + 2 * sub);  // Ph*Vl
            }
        }
        __syncthreads();   // S dead -> O region reuse safe
        if (pk == 0) {
#pragma unroll
            for (int mi = 0; mi < 3; mi++)
#pragma unroll
                for (int nj = 0; nj < 4; nj++)
#pragma unroll
                    for (int rr = 0; rr < 2; rr++) {
                        const int n = pn * 48 + mi * 16 + g + rr * 8;
                        const int d = pd * 32 + nj * 8 + 2 * l4;
                        if (n < NN)
                            *(float2*)(Of + n * OSTRIDE + d) =
                                make_float2(ov[mi][nj][rr * 2], ov[mi][nj][rr * 2 + 1]);
                    }
        }
        __syncthreads();
        if (pk == 1) {
#pragma unroll
            for (int mi = 0; mi < 3; mi++)
#pragma unroll
                for (int nj = 0; nj < 4; nj++)
#pragma unroll
                    for (int rr = 0; rr < 2; rr++) {
                        const int n = pn * 48 + mi * 16 + g + rr * 8;
                        const int d = pd * 32 + nj * 8 + 2 * l4;
                        if (n < NN) {
                            float2 v = *(float2*)(Of + n * OSTRIDE + d);
                            float o0 = v.x + ov[mi][nj][rr * 2];
                            float o1 = v.y + ov[mi][nj][rr * 2 + 1];
                            float* dst = out + ((size_t)b * DM + h64 + d) * NN + n;
                            dst[0]  = o0;
                            dst[NN] = o1;
                        }
                    }
        }
    }
}

// ---------------------------------------------------------------------------
extern "C" void kernel_launch(void* const* d_in, const int* in_sizes, int n_in,
                              void* d_out, int out_size) {
    const float* x     = (const float*)d_in[0];
    const float* qkv_w = (const float*)d_in[1];
    const float* qkv_b = (const float*)d_in[2];
    const float* rel_h = (const float*)d_in[3];
    const float* rel_w = (const float*)d_in[4];
    float* out = (float*)d_out;

    cudaFuncSetAttribute(fused_mhsa, cudaFuncAttributeMaxDynamicSharedMemorySize, SMEM_FUSED);

    prep_w<<<OC * DM / 256, 256>>>(qkv_w);
    prep_x<<<dim3(BB, DM / 64), 256>>>(x);
    fused_mhsa<<<BB * NH, 256, SMEM_FUSED>>>(qkv_b, rel_h, rel_w, out);
}

// round 14
// speedup vs baseline: 1.7433x; 1.0349x over previous
#include <cuda_runtime.h>
#include <cuda_fp16.h>
#include <math.h>
#include <stdint.h>

// Problem constants
#define BB   1024
#define DM   512
#define NH   8
#define HD   64
#define NN   81
#define OC   1536

// Phase-1 GEMM staging
#define KT     32
#define NTILES (DM / KT)     // 16
#define RSTRIDE 80           // 64B data + 16B pad
#define WROWS  192
#define XROWS  96
#define WTILE  (WROWS * RSTRIDE)        // 15360
#define XTILE  (XROWS * RSTRIDE)        // 7680
#define STG_BYTES (WTILE + XTILE)       // 23040
#define STAGES    (2 * STG_BYTES)       // 46080

// fp16 planes
#define QKSTRIDE 144         // Q/K: 96 rows x (128B data + 16 pad)
#define VSTRIDE  208         // V: 64 rows, P: 96 rows x (192B data + 16 pad)
#define QKPLANE  (96 * QKSTRIDE)        // 13824
#define VPLANE   (64 * VSTRIDE)         // 13312

#define SP       84          // S row stride (floats)

// smem map
#define R0_VH   0
#define R0_VL   VPLANE
#define R0_S    (2 * VPLANE)                 // 26624 (stages dead by then)
#define R0_SIZE (R0_S + 82 * SP * 4)         // 54176
#define OFF_QH  (R0_SIZE)                    // Q hi only
#define OFF_KH  (R0_SIZE + QKPLANE)
#define OFF_KL  (R0_SIZE + 2 * QKPLANE)
#define OFF_PH  (R0_SIZE)                    // P overlays Q (+dead K-hi) after scores
#define SMEM_FUSED (R0_SIZE + 3 * QKPLANE)   // 95648 -> 2 CTAs/SM

// Scratch (fp16 inputs only)
__device__ __half g_wh[(size_t)OC * DM];
__device__ __half g_xh[(size_t)BB * 96 * DM];

__device__ __forceinline__ uint32_t smem_u32(const void* p) {
    uint32_t a;
    asm("{ .reg .u64 t; cvta.to.shared.u64 t, %1; cvt.u32.u64 %0, t; }" : "=r"(a) : "l"(p));
    return a;
}

#define CP16(dst, src) \
    asm volatile("cp.async.cg.shared.global [%0], [%1], 16;" :: "r"(dst), "l"(src))
#define CP_COMMIT() asm volatile("cp.async.commit_group;" ::: "memory")
#define CP_WAIT(n)  asm volatile("cp.async.wait_group %0;" :: "n"(n) : "memory")

#define LDSM4(r0, r1, r2, r3, addr)                                           \
    asm volatile("ldmatrix.sync.aligned.m8n8.x4.shared.b16 {%0,%1,%2,%3}, [%4];" \
        : "=r"(r0), "=r"(r1), "=r"(r2), "=r"(r3) : "r"(addr))

#define LDSM2(r0, r1, addr)                                                   \
    asm volatile("ldmatrix.sync.aligned.m8n8.x2.shared.b16 {%0,%1}, [%2];"    \
        : "=r"(r0), "=r"(r1) : "r"(addr))

#define MMA_F16(C, A, B)                                                      \
    asm volatile(                                                             \
        "mma.sync.aligned.m16n8k16.row.col.f32.f16.f16.f32 "                  \
        "{%0,%1,%2,%3}, {%4,%5,%6,%7}, {%8,%9}, {%0,%1,%2,%3};\n"             \
        : "+f"((C)[0]), "+f"((C)[1]), "+f"((C)[2]), "+f"((C)[3])              \
        : "r"((A)[0]), "r"((A)[1]), "r"((A)[2]), "r"((A)[3]),                 \
          "r"((B)[0]), "r"((B)[1]))

// split v into fp16 hi + lo, store half2-packed pair to hi/lo planes
__device__ __forceinline__ void split_store(char* smem, int offH, int offL,
                                            int byteoff, float v0, float v1) {
    __half h0 = __float2half_rn(v0);
    __half h1 = __float2half_rn(v1);
    float  l0 = v0 - __half2float(h0);
    float  l1 = v1 - __half2float(h1);
    *(__half2*)(smem + offH + byteoff) = __halves2half2(h0, h1);
    *(__half2*)(smem + offL + byteoff) =
        __halves2half2(__float2half_rn(l0), __float2half_rn(l1));
}

// ---------------------------------------------------------------------------
__global__ void prep_w(const float* __restrict__ w) {
    int i = blockIdx.x * 256 + threadIdx.x;
    g_wh[i] = __float2half_rn(w[i]);
}

__global__ __launch_bounds__(256) void prep_x(const float* __restrict__ x) {
    __shared__ float ts[64][83];
    const int b  = blockIdx.x;
    const int c0 = blockIdx.y * 64;
    const int tid = threadIdx.x;

    const float* xb = x + ((size_t)b * DM + c0) * NN;
    for (int idx = tid; idx < 64 * NN; idx += 256) {
        int c = idx / NN;
        int n = idx - c * NN;
        ts[c][n] = xb[(size_t)c * NN + n];
    }
    __syncthreads();

    for (int idx = tid; idx < 96 * 64; idx += 256) {
        int n = idx >> 6;
        int c = idx & 63;
        float v = (n < NN) ? ts[c][n] : 0.0f;
        g_xh[((size_t)b * 96 + n) * DM + c0 + c] = __float2half_rn(v);
    }
}

// ---------------------------------------------------------------------------
// Stage loader: W rows (Q|K|V for head h) + X rows for batch b
// ---------------------------------------------------------------------------
__device__ __forceinline__ void load_stage(uint32_t sb, int stage,
                                           int k0, int h64, int b, int tid) {
    const uint32_t base = sb + stage * STG_BYTES;
#pragma unroll
    for (int i = 0; i < 3; i++) {                // W: 768 chunks
        int idx = tid + i * 256;
        int row = idx >> 2;
        int chv = idx & 3;
        int o   = (row >> 6) * DM + h64 + (row & 63);
        const __half* src = g_wh + (size_t)o * DM + k0 + chv * 8;
        CP16(base + row * RSTRIDE + chv * 16, src);
    }
#pragma unroll
    for (int i = 0; i < 2; i++) {                // X: 384 chunks
        int idx = tid + i * 256;
        if (idx < 384) {
            int row = idx >> 2;
            int chv = idx & 3;
            const __half* src = g_xh + ((size_t)b * 96 + row) * DM + k0 + chv * 8;
            CP16(base + WTILE + row * RSTRIDE + chv * 16, src);
        }
    }
    CP_COMMIT();
}

// ---------------------------------------------------------------------------
// Fused kernel: QKV GEMM + scores (2-term) + softmax + PV (2-term), fp16 HMMA
// Phases 2/3 re-tiled so each warp owns a unique output region (no combines).
// ---------------------------------------------------------------------------
__global__ __launch_bounds__(256, 2) void fused_mhsa(const float* __restrict__ bias,
                                                     const float* __restrict__ rel_h,
                                                     const float* __restrict__ rel_w,
                                                     float* __restrict__ out) {
    extern __shared__ char smem[];
    const uint32_t sb = smem_u32(smem);
    float* Sf = (float*)(smem + R0_S);

    const int tid  = threadIdx.x;
    const int bh   = blockIdx.x;
    const int b    = bh >> 3;
    const int h64  = (bh & 7) * HD;
    const int warp = tid >> 5;
    const int lane = tid & 31;
    const int g    = lane >> 2;
    const int l4   = lane & 3;

    const uint32_t arow = (lane & 7) + ((lane >> 3) & 1) * 8;
    const uint32_t acol = (lane >> 4) * 16;
    const uint32_t brow = (lane & 7) + ((lane >> 4) & 1) * 8;
    const uint32_t bcol = ((lane >> 3) & 1) * 16;
    const uint32_t aoff80  = arow * 80  + acol;
    const uint32_t boff80  = brow * 80  + bcol;
    const uint32_t aoff144 = arow * 144 + acol;
    const uint32_t boff144 = brow * 144 + bcol;
    const uint32_t aoff208 = arow * 208 + acol;
    const uint32_t boff208 = brow * 208 + bcol;
    const uint32_t b2off   = (lane & 7);             // LDSM2 row part
    const uint32_t b2col   = ((lane >> 3) & 1) * 16; // LDSM2 col part

    // ================= Phase 1: QKV projection =================
    const int wA = warp & 1;    // M half
    const int wB = warp >> 1;   // N quarter (0..3)

    float qk[3][4][4];
    float vv[2][3][4];
#pragma unroll
    for (int i = 0; i < 3; i++)
#pragma unroll
        for (int j = 0; j < 4; j++)
#pragma unroll
            for (int r = 0; r < 4; r++) qk[i][j][r] = 0.0f;
#pragma unroll
    for (int i = 0; i < 2; i++)
#pragma unroll
        for (int j = 0; j < 3; j++)
#pragma unroll
            for (int r = 0; r < 4; r++) vv[i][j][r] = 0.0f;

    load_stage(sb, 0, 0, h64, b, tid);
    load_stage(sb, 1, KT, h64, b, tid);

    for (int ch = 0; ch < NTILES; ch++) {
        if (ch + 1 < NTILES) { CP_WAIT(1); } else { CP_WAIT(0); }
        __syncthreads();

        const uint32_t Wt = sb + (ch & 1) * STG_BYTES;
        const uint32_t Xt = Wt + WTILE;

#pragma unroll
        for (int ks = 0; ks < 2; ks++) {
            const uint32_t kb = ks * 32;
            // --- QK ---
            uint32_t a[3][4];
#pragma unroll
            for (int mi = 0; mi < 3; mi++)
                LDSM4(a[mi][0], a[mi][1], a[mi][2], a[mi][3],
                      Xt + (uint32_t)((wA * 48 + mi * 16) * 80) + kb + aoff80);
            uint32_t bw[2][4];
#pragma unroll
            for (int pr = 0; pr < 2; pr++)
                LDSM4(bw[pr][0], bw[pr][1], bw[pr][2], bw[pr][3],
                      Wt + (uint32_t)((wB * 32 + pr * 16) * 80) + kb + boff80);
#pragma unroll
            for (int pr = 0; pr < 2; pr++)
#pragma unroll
                for (int sub = 0; sub < 2; sub++)
#pragma unroll
                    for (int mi = 0; mi < 3; mi++)
                        MMA_F16(qk[mi][pr * 2 + sub], a[mi], bw[pr] + 2 * sub);
            // --- V ---
            uint32_t av[2][4];
#pragma unroll
            for (int mi = 0; mi < 2; mi++)
                LDSM4(av[mi][0], av[mi][1], av[mi][2], av[mi][3],
                      Wt + (uint32_t)((128 + wA * 32 + mi * 16) * 80) + kb + aoff80);
            uint32_t bx0[4], bx2[2];
            LDSM4(bx0[0], bx0[1], bx0[2], bx0[3],
                  Xt + (uint32_t)((wB * 24) * 80) + kb + boff80);
            LDSM2(bx2[0], bx2[1],
                  Xt + (uint32_t)((wB * 24 + 16 + b2off) * 80) + kb + b2col);
#pragma unroll
            for (int mi = 0; mi < 2; mi++) {
                MMA_F16(vv[mi][0], av[mi], bx0 + 0);
                MMA_F16(vv[mi][1], av[mi], bx0 + 2);
                MMA_F16(vv[mi][2], av[mi], bx2);
            }
        }

        if (ch + 2 < NTILES) {
            __syncthreads();
            load_stage(sb, ch & 1, (ch + 2) * KT, h64, b, tid);
        }
    }
    __syncthreads();   // stages dead; planes live below

    // ---- Epilogue 1a: Q (hi only) / K (hi+lo) -> fp16 planes [token][d] ----
#pragma unroll
    for (int mi = 0; mi < 3; mi++) {
#pragma unroll
        for (int rr = 0; rr < 2; rr++) {
            const int tok = wA * 48 + mi * 16 + g + rr * 8;
            const int tc  = (tok < NN) ? tok : 80;
#pragma unroll
            for (int ni = 0; ni < 4; ni++) {
                const int o  = wB * 32 + ni * 8 + 2 * l4;
                float c0 = qk[mi][ni][rr * 2 + 0];
                float c1 = qk[mi][ni][rr * 2 + 1];
                if (wB < 2) {          // Q: single fp16 plane
                    c0 += bias[h64 + o];
                    c1 += bias[h64 + o + 1];
                    *(__half2*)(smem + OFF_QH + tok * QKSTRIDE + 2 * o) =
                        __halves2half2(__float2half_rn(c0), __float2half_rn(c1));
                } else {               // K (+rel fold): hi/lo split
                    const int d = o - 64;
                    c0 += bias[512 + h64 + d]
                        + rel_h[(h64 + d) * 9 + tc % 9] + rel_w[(h64 + d) * 9 + tc / 9];
                    c1 += bias[512 + h64 + d + 1]
                        + rel_h[(h64 + d + 1) * 9 + tc % 9] + rel_w[(h64 + d + 1) * 9 + tc / 9];
                    split_store(smem, OFF_KH, OFF_KL, tok * QKSTRIDE + 2 * d, c0, c1);
                }
            }
        }
    }
    // ---- Epilogue 1b: V accums -> fp16 hi/lo planes [d][token] ----
#pragma unroll
    for (int mi = 0; mi < 2; mi++) {
#pragma unroll
        for (int rr = 0; rr < 2; rr++) {
            const int d  = wA * 32 + mi * 16 + g + rr * 8;
            const float bv = bias[1024 + h64 + d];
#pragma unroll
            for (int ni = 0; ni < 3; ni++) {
                const int tok = wB * 24 + ni * 8 + 2 * l4;
                split_store(smem, R0_VH, R0_VL, d * VSTRIDE + 2 * tok,
                            vv[mi][ni][rr * 2] + bv, vv[mi][ni][rr * 2 + 1] + bv);
            }
        }
    }
    __syncthreads();

    // ===== Phase 2: S = Qh.(Kh+Kl)^T — warps n(2) x m(4), full k, no combine
    {
        const int sn  = warp & 1;      // n half (48 rows of Q)
        const int sm2 = warp >> 1;     // m quarter (24 rows of K)
        float sc[3][3][4];
#pragma unroll
        for (int i = 0; i < 3; i++)
#pragma unroll
            for (int j = 0; j < 3; j++)
#pragma unroll
                for (int r = 0; r < 4; r++) sc[i][j][r] = 0.0f;

#pragma unroll
        for (int ks = 0; ks < 4; ks++) {
            const uint32_t kb = ks * 32;
            uint32_t ah[3][4];
#pragma unroll
            for (int mi = 0; mi < 3; mi++)
                LDSM4(ah[mi][0], ah[mi][1], ah[mi][2], ah[mi][3],
                      sb + OFF_QH + (uint32_t)((sn * 48 + mi * 16) * QKSTRIDE) + kb + aoff144);
            uint32_t bk4[4], bk2[2];
            // K hi
            LDSM4(bk4[0], bk4[1], bk4[2], bk4[3],
                  sb + OFF_KH + (uint32_t)((sm2 * 24) * QKSTRIDE) + kb + boff144);
            LDSM2(bk2[0], bk2[1],
                  sb + OFF_KH + (uint32_t)((sm2 * 24 + 16 + b2off) * QKSTRIDE) + kb + b2col);
#pragma unroll
            for (int sub = 0; sub < 2; sub++)
#pragma unroll
                for (int mi = 0; mi < 3; mi++)
                    MMA_F16(sc[mi][sub], ah[mi], bk4 + 2 * sub);
#pragma unroll
            for (int mi = 0; mi < 3; mi++)
                MMA_F16(sc[mi][2], ah[mi], bk2);
            // K lo
            LDSM4(bk4[0], bk4[1], bk4[2], bk4[3],
                  sb + OFF_KL + (uint32_t)((sm2 * 24) * QKSTRIDE) + kb + boff144);
            LDSM2(bk2[0], bk2[1],
                  sb + OFF_KL + (uint32_t)((sm2 * 24 + 16 + b2off) * QKSTRIDE) + kb + b2col);
#pragma unroll
            for (int sub = 0; sub < 2; sub++)
#pragma unroll
                for (int mi = 0; mi < 3; mi++)
                    MMA_F16(sc[mi][sub], ah[mi], bk4 + 2 * sub);
#pragma unroll
            for (int mi = 0; mi < 3; mi++)
                MMA_F16(sc[mi][2], ah[mi], bk2);
        }
        // direct unique write to S
#pragma unroll
        for (int mi = 0; mi < 3; mi++)
#pragma unroll
            for (int nt = 0; nt < 3; nt++)
#pragma unroll
                for (int rr = 0; rr < 2; rr++) {
                    const int n = sn * 48 + mi * 16 + g + rr * 8;
                    const int m = sm2 * 24 + nt * 8 + 2 * l4;
                    if (n < 82 && m < 82)
                        *(float2*)(Sf + n * SP + m) =
                            make_float2(sc[mi][nt][rr * 2], sc[mi][nt][rr * 2 + 1]);
                }
    }
    __syncthreads();

    // ---- softmax (warp per row) fused with Ph fp16 write + zero-pad cols ----
    for (int r = warp; r < NN; r += 8) {
        float* row = Sf + r * SP;
        float mx = -1e30f;
        for (int m = lane; m < NN; m += 32) mx = fmaxf(mx, row[m]);
#pragma unroll
        for (int s = 16; s > 0; s >>= 1)
            mx = fmaxf(mx, __shfl_xor_sync(0xFFFFFFFF, mx, s));
        float sum = 0.0f;
        for (int m = lane; m < NN; m += 32) {
            float e = __expf(row[m] - mx);
            row[m] = e;
            sum += e;
        }
#pragma unroll
        for (int s = 16; s > 0; s >>= 1)
            sum += __shfl_xor_sync(0xFFFFFFFF, sum, s);
        float inv = 1.0f / sum;
        for (int m = lane; m < 96; m += 32) {
            float v = (m < NN) ? row[m] * inv : 0.0f;
            *(__half*)(smem + OFF_PH + r * VSTRIDE + 2 * m) = __float2half_rn(v);
        }
    }
    __syncthreads();

    // ===== Phase 3: O = Ph.(Vh+Vl) — warps n(2) x d(4), full k, direct gmem
    {
        const int pn  = warp & 1;      // n half (48)
        const int pd2 = warp >> 1;     // d quarter (16)
        float ov[3][2][4];
#pragma unroll
        for (int i = 0; i < 3; i++)
#pragma unroll
            for (int j = 0; j < 2; j++)
#pragma unroll
                for (int r = 0; r < 4; r++) ov[i][j][r] = 0.0f;

#pragma unroll
        for (int ks = 0; ks < 6; ks++) {
            const uint32_t kb = ks * 32;
            uint32_t a[3][4];
#pragma unroll
            for (int mi = 0; mi < 3; mi++)
                LDSM4(a[mi][0], a[mi][1], a[mi][2], a[mi][3],
                      sb + OFF_PH + (uint32_t)((pn * 48 + mi * 16) * VSTRIDE) + kb + aoff208);
            uint32_t bv4[4];
            LDSM4(bv4[0], bv4[1], bv4[2], bv4[3],
                  sb + R0_VH + (uint32_t)((pd2 * 16) * VSTRIDE) + kb + boff208);
#pragma unroll
            for (int sub = 0; sub < 2; sub++)
#pragma unroll
                for (int mi = 0; mi < 3; mi++)
                    MMA_F16(ov[mi][sub], a[mi], bv4 + 2 * sub);   // Ph*Vh
            LDSM4(bv4[0], bv4[1], bv4[2], bv4[3],
                  sb + R0_VL + (uint32_t)((pd2 * 16) * VSTRIDE) + kb + boff208);
#pragma unroll
            for (int sub = 0; sub < 2; sub++)
#pragma unroll
                for (int mi = 0; mi < 3; mi++)
                    MMA_F16(ov[mi][sub], a[mi], bv4 + 2 * sub);   // Ph*Vl
        }
        // direct unique write to gmem
#pragma unroll
        for (int mi = 0; mi < 3; mi++)
#pragma unroll
            for (int sub = 0; sub < 2; sub++)
#pragma unroll
                for (int rr = 0; rr < 2; rr++) {
                    const int n = pn * 48 + mi * 16 + g + rr * 8;
                    const int d = pd2 * 16 + sub * 8 + 2 * l4;
                    if (n < NN) {
                        float* dst = out + ((size_t)b * DM + h64 + d) * NN + n;
                        dst[0]  = ov[mi][sub][rr * 2];
                        dst[NN] = ov[mi][sub][rr * 2 + 1];
                    }
                }
    }
}

// ---------------------------------------------------------------------------
extern "C" void kernel_launch(void* const* d_in, const int* in_sizes, int n_in,
                              void* d_out, int out_size) {
    const float* x     = (const float*)d_in[0];
    const float* qkv_w = (const float*)d_in[1];
    const float* qkv_b = (const float*)d_in[2];
    const float* rel_h = (const float*)d_in[3];
    const float* rel_w = (const float*)d_in[4];
    float* out = (float*)d_out;

    cudaFuncSetAttribute(fused_mhsa, cudaFuncAttributeMaxDynamicSharedMemorySize, SMEM_FUSED);

    prep_w<<<OC * DM / 256, 256>>>(qkv_w);
    prep_x<<<dim3(BB, DM / 64), 256>>>(x);
    fused_mhsa<<<BB * NH, 256, SMEM_FUSED>>>(qkv_b, rel_h, rel_w, out);
}